// round 12
// baseline (speedup 1.0000x reference)
#include <cuda_runtime.h>
#include <math.h>

#define EPS 1e-8f
#define LN_EPS 1e-5f
#define CHUNK 32

typedef unsigned long long ull;

// ---------------- packed f32x2 helpers (sm_103a) ----------------
__device__ __forceinline__ ull pack2(float lo, float hi){
    ull r; asm("mov.b64 %0, {%1,%2};" : "=l"(r) : "f"(lo), "f"(hi)); return r;
}
__device__ __forceinline__ void unpack2(ull v, float &lo, float &hi){
    asm("mov.b64 {%0,%1}, %2;" : "=f"(lo), "=f"(hi) : "l"(v));
}
__device__ __forceinline__ ull ffma2(ull a, ull b, ull c){
    ull d; asm("fma.rn.f32x2 %0, %1, %2, %3;" : "=l"(d) : "l"(a), "l"(b), "l"(c)); return d;
}
__device__ __forceinline__ ull fmul2(ull a, ull b){
    ull d; asm("mul.rn.f32x2 %0, %1, %2;" : "=l"(d) : "l"(a), "l"(b)); return d;
}
__device__ __forceinline__ ull fadd2(ull a, ull b){
    ull d; asm("add.rn.f32x2 %0, %1, %2;" : "=l"(d) : "l"(a), "l"(b)); return d;
}
__device__ __forceinline__ float hsum2(ull v){ float lo, hi; unpack2(v, lo, hi); return lo + hi; }

// ---------------- scratch (static __device__, no allocs) ----------------
__device__ __align__(16) float  g_q[16*512*64];
__device__ __align__(16) float  g_z[16*512*64];
__device__ __align__(16) float  g_v[16*512*64];
__device__ __align__(16) float  g_part[16*16*4160];
__device__ float4 g_pack [16*4096];   // {wx=sg, wy=sb+Ps_ln, wz=ng, ww=nb+Mprev_ln}
__device__ float4 g_pack2[16*4096];   // {wx*wz, wy*wz, wz, ww}  (pass-2 pack)
__device__ float  g_Pz[16*64];        // P_z_ln last step per batch
__device__ double g_acc[2];           // sum, sumsq for std

__device__ __forceinline__ float eluf(float x){ return x > 0.f ? x : (expf(x) - 1.f); }

// one-sync block reduce for 256 threads (8 warps). Results broadcast to ALL
// threads in out[]. red: >= 8*N floats.
template<int N>
__device__ __forceinline__ void block_reduce_b(const float* v, float* red, float* out){
    int lane = threadIdx.x & 31, w = threadIdx.x >> 5;
    #pragma unroll
    for (int i = 0; i < N; i++){
        float x = v[i];
        #pragma unroll
        for (int o = 16; o; o >>= 1) x += __shfl_xor_sync(0xffffffffu, x, o);
        if (lane == 0) red[w*N + i] = x;
    }
    __syncthreads();
    #pragma unroll
    for (int i = 0; i < N; i++){
        float s = 0.f;
        #pragma unroll
        for (int ww2 = 0; ww2 < 8; ww2++) s += red[ww2*N + i];
        out[i] = s;
    }
}

// ---------------- fused front kernel, 3 branches:
//  blocks [0,B)            : prompt/history precompute
//  blocks [B, B+NPH)       : z/v GEMVs + per-chunk outer-product partials
//  blocks [B+NPH, B+2*NPH) : q GEMV
__global__ __launch_bounds__(256, 4)
void k_front(const int* uid, const float* X, const float* Pm, const float* Sm,
             const float* Wq, const float* bq, const float* Wk, const float* bk,
             const float* Wv, const float* bv,
             const float* zg, const float* zb, const float* sg, const float* sb,
             const float* ng, const float* nb,
             const float* pzbuf, const float* psbuf, int NCH, int LP, int B)
{
    __shared__ __align__(16) float SBUF[11360];
    int tid = threadIdx.x;
    int bi = blockIdx.x;

    if (bi >= B && bi < B + B*NCH){
        // ---------------- z/v branch ----------------
        float* xsT  = SBUF;            // 64*36 transposed X chunk
        float* zbuf = SBUF + 2304;     // 32*64
        float* vbuf = SBUF + 4352;     // 32*64

        int pid = bi - B;
        int b = pid / NCH, ch = pid % NCH;
        int L = NCH * CHUNK;
        size_t xbase = ((size_t)b*L + (size_t)ch*CHUNK) * 64;

        #pragma unroll
        for (int i = 0; i < 8; i++){
            int e = tid + i*256;
            int l = e >> 6, k = e & 63;
            xsT[k*36 + l] = X[xbase + e];
        }
        __syncthreads();

        {
            int col = tid & 63, grp = tid >> 6;   // rows grp*8 .. grp*8+7
            float bkv = bk[col], bvv = bv[col];
            ull az[4], av[4];
            ull bz2 = pack2(bkv, bkv), bv2 = pack2(bvv, bvv);
            #pragma unroll
            for (int j = 0; j < 4; j++){ az[j] = bz2; av[j] = bv2; }
            #pragma unroll 4
            for (int k = 0; k < 64; k++){
                float wk = Wk[k*64 + col];
                float wv = Wv[k*64 + col];
                ull wkp = pack2(wk, wk), wvp = pack2(wv, wv);
                const ulonglong2* xr = (const ulonglong2*)&xsT[k*36 + grp*8];
                ulonglong2 x0 = xr[0], x1 = xr[1];
                az[0] = ffma2(x0.x, wkp, az[0]); az[1] = ffma2(x0.y, wkp, az[1]);
                az[2] = ffma2(x1.x, wkp, az[2]); az[3] = ffma2(x1.y, wkp, az[3]);
                av[0] = ffma2(x0.x, wvp, av[0]); av[1] = ffma2(x0.y, wvp, av[1]);
                av[2] = ffma2(x1.x, wvp, av[2]); av[3] = ffma2(x1.y, wvp, av[3]);
            }
            #pragma unroll
            for (int j = 0; j < 4; j++){
                int row = grp*8 + 2*j;
                float a, b2; unpack2(az[j], a, b2);
                float za = eluf(a), zb2v = eluf(b2);
                zbuf[row*64 + col] = za;        g_z[xbase + row*64 + col] = za;
                zbuf[(row+1)*64 + col] = zb2v;  g_z[xbase + (row+1)*64 + col] = zb2v;
                unpack2(av[j], a, b2);
                vbuf[row*64 + col] = a;         g_v[xbase + row*64 + col] = a;
                vbuf[(row+1)*64 + col] = b2;    g_v[xbase + (row+1)*64 + col] = b2;
            }
        }
        __syncthreads();

        int p = tid & 63, d0 = (tid >> 6) * 16;
        ull acc2o[8];
        #pragma unroll
        for (int j = 0; j < 8; j++) acc2o[j] = 0ull;
        #pragma unroll 4
        for (int l = 0; l < 32; l++){
            float vv = vbuf[l*64 + p];
            ull vvp = pack2(vv, vv);
            const ulonglong2* zb2p = (const ulonglong2*)&zbuf[l*64 + d0];
            #pragma unroll
            for (int j4 = 0; j4 < 4; j4++){
                ulonglong2 zz = zb2p[j4];
                acc2o[j4*2+0] = ffma2(zz.x, vvp, acc2o[j4*2+0]);
                acc2o[j4*2+1] = ffma2(zz.y, vvp, acc2o[j4*2+1]);
            }
        }
        size_t o = (size_t)(b*NCH + ch) * 4160;
        #pragma unroll
        for (int j = 0; j < 8; j++){
            float a, b2; unpack2(acc2o[j], a, b2);
            g_part[o + (d0 + 2*j  )*64 + p] = a;
            g_part[o + (d0 + 2*j+1)*64 + p] = b2;
        }
        if (tid < 64){
            float zs = 0.f;
            #pragma unroll 4
            for (int l = 0; l < 32; l++) zs += zbuf[l*64 + tid];
            g_part[o + 4096 + tid] = zs;
        }
        return;
    }

    if (bi >= B + B*NCH){
        // ---------------- q branch ----------------
        float* xsT = SBUF;
        int pid = bi - B - B*NCH;
        int b = pid / NCH, ch = pid % NCH;
        int L = NCH * CHUNK;
        size_t xbase = ((size_t)b*L + (size_t)ch*CHUNK) * 64;

        #pragma unroll
        for (int i = 0; i < 8; i++){
            int e = tid + i*256;
            int l = e >> 6, k = e & 63;
            xsT[k*36 + l] = X[xbase + e];
        }
        __syncthreads();

        int col = tid & 63, grp = tid >> 6;
        float bqv = bq[col];
        ull aq[4];
        ull bq2 = pack2(bqv, bqv);
        #pragma unroll
        for (int j = 0; j < 4; j++) aq[j] = bq2;
        #pragma unroll 4
        for (int k = 0; k < 64; k++){
            float wq = Wq[k*64 + col];
            ull wqp = pack2(wq, wq);
            const ulonglong2* xr = (const ulonglong2*)&xsT[k*36 + grp*8];
            ulonglong2 x0 = xr[0], x1 = xr[1];
            aq[0] = ffma2(x0.x, wqp, aq[0]); aq[1] = ffma2(x0.y, wqp, aq[1]);
            aq[2] = ffma2(x1.x, wqp, aq[2]); aq[3] = ffma2(x1.y, wqp, aq[3]);
        }
        #pragma unroll
        for (int j = 0; j < 4; j++){
            int row = grp*8 + 2*j;
            float a, b2; unpack2(aq[j], a, b2);
            g_q[xbase + row*64 + col]     = eluf(a);
            g_q[xbase + (row+1)*64 + col] = eluf(b2);
        }
        return;
    }

    // ---------------- prompt branch (blocks [0,B)) ----------------
    float* xsA  = SBUF;          float* xsB  = SBUF + 512;
    float* zbA  = SBUF + 1024;   float* zbB  = SBUF + 1536;
    float* vbA  = SBUF + 2048;   float* vbB  = SBUF + 2560;
    float* bufA = SBUF + 3072;   float* bufB = SBUF + 7168;
    float* zl   = SBUF + 11264;
    float* redA = SBUF + 11328;  float* redB = SBUF + 11344;

    int b = bi;
    int p = tid & 63, d0 = (tid >> 6) * 16;

    if (b == 0 && tid == 0){ g_acc[0] = 0.0; g_acc[1] = 0.0; }

    for (int i = tid; i < 512; i += 256){ xsA[i] = 0.f; xsB[i] = 0.f; }
    for (int i = tid; i < LP*64; i += 256){
        xsA[i] = Pm[b*LP*64 + i];
        xsB[i] = Sm[b*LP*64 + i];
    }
    __syncthreads();

    {
        int pass = tid >> 7, dt = (tid >> 6) & 1, col = tid & 63;
        const float* xp = pass ? xsB : xsA;
        float* zp = pass ? zbB : zbA;
        float* vp = pass ? vbB : vbA;
        const float* W  = dt ? Wv : Wk;
        float bb = dt ? bv[col] : bk[col];
        float acc8[8];
        #pragma unroll
        for (int l = 0; l < 8; l++) acc8[l] = bb;
        #pragma unroll 4
        for (int k = 0; k < 64; k++){
            float w = W[k*64 + col];
            #pragma unroll
            for (int l = 0; l < 8; l++) acc8[l] += xp[l*64 + k] * w;
        }
        if (dt == 0){
            #pragma unroll
            for (int l = 0; l < 8; l++) zp[l*64 + col] = eluf(acc8[l]);
        } else {
            #pragma unroll
            for (int l = 0; l < 8; l++) vp[l*64 + col] = acc8[l];
        }
    }
    __syncthreads();

    float accP[16], accS[16];
    #pragma unroll
    for (int i = 0; i < 16; i++){ accP[i] = 0.f; accS[i] = 0.f; }
    for (int l = 0; l < LP; l++){
        float vvP = vbA[l*64 + p], vvS = vbB[l*64 + p];
        #pragma unroll
        for (int i = 0; i < 16; i++){
            accP[i] += zbA[l*64 + d0 + i] * vvP;
            accS[i] += zbB[l*64 + d0 + i] * vvS;
        }
    }
    float zsP = 0.f, zsS = 0.f;
    if (tid < 64){
        for (int l = 0; l < LP; l++){ zsP += zbA[l*64 + tid]; zsS += zbB[l*64 + tid]; }
    }

    float rv[2], out2[2];
    rv[0] = (tid < 64) ? zsP : 0.f; rv[1] = (tid < 64) ? zsP*zsP : 0.f;
    block_reduce_b<2>(rv, redA, out2);
    {
        float mz = out2[0]*(1.f/64.f);
        float ivz = rsqrtf(out2[1]*(1.f/64.f) - mz*mz + LN_EPS);
        if (tid < 64) g_Pz[b*64 + tid] = (zsP - mz)*ivz*zg[tid] + zb[tid];
    }
    rv[0] = (tid < 64) ? zsS : 0.f; rv[1] = (tid < 64) ? zsS*zsS : 0.f;
    block_reduce_b<2>(rv, redB, out2);
    {
        float mz = out2[0]*(1.f/64.f);
        float ivz = rsqrtf(out2[1]*(1.f/64.f) - mz*mz + LN_EPS);
        if (tid < 64) zl[tid] = (zsS - mz)*ivz*zg[tid] + zb[tid];
    }
    float sv[2];
    sv[0] = 0.f; sv[1] = 0.f;
    #pragma unroll
    for (int i = 0; i < 16; i++){ sv[0] += accP[i]; sv[1] += accP[i]*accP[i]; }
    block_reduce_b<2>(sv, redA, out2);
    {
        float ms = out2[0]*(1.f/4096.f);
        float ivs = rsqrtf(out2[1]*(1.f/4096.f) - ms*ms + LN_EPS);
        #pragma unroll
        for (int i = 0; i < 16; i++){
            int e = (d0 + i)*64 + p;
            bufA[e] = (accP[i] - ms)*ivs*sg[e] + sb[e];
        }
    }
    sv[0] = 0.f; sv[1] = 0.f;
    #pragma unroll
    for (int i = 0; i < 16; i++){ sv[0] += accS[i]; sv[1] += accS[i]*accS[i]; }
    block_reduce_b<2>(sv, redB, out2);
    {
        float ms = out2[0]*(1.f/4096.f);
        float ivs = rsqrtf(out2[1]*(1.f/4096.f) - ms*ms + LN_EPS);
        #pragma unroll
        for (int i = 0; i < 16; i++){
            int e = (d0 + i)*64 + p;
            bufB[e] = (accS[i] - ms)*ivs*sg[e] + sb[e];
        }
    }
    __syncthreads();

    int u = uid[b];
    float pzv = 0.f;
    if (tid < 64) pzv = pzbuf[(size_t)u*64 + tid] + zl[tid];
    float rv1[1], out1[1];
    rv1[0] = (tid < 64) ? pzv*pzv : 0.f;
    block_reduce_b<1>(rv1, redA, out1);
    float ipn = 1.f / (fmaxf(sqrtf(out1[0]), 1e-8f) + EPS);

    float pn16[16];
    sv[0] = 0.f; sv[1] = 0.f;
    #pragma unroll
    for (int k2 = 0; k2 < 16; k2++){
        int e = tid + k2*256;
        float pv = (psbuf[(size_t)u*4096 + e] + bufB[e]) * ipn;
        pn16[k2] = pv; sv[0] += pv; sv[1] += pv*pv;
    }
    block_reduce_b<2>(sv, redB, out2);
    float mp = out2[0]*(1.f/4096.f);
    float ivp = rsqrtf(out2[1]*(1.f/4096.f) - mp*mp + LN_EPS);
    #pragma unroll
    for (int k2 = 0; k2 < 16; k2++){
        int e = tid + k2*256;
        float M = (pn16[k2] - mp)*ivp*ng[e] + nb[e];
        float wxv = sg[e], wyv = sb[e] + bufA[e];
        float wzv = ng[e], wwv = nb[e] + M;
        g_pack [b*4096 + e] = make_float4(wxv, wyv, wzv, wwv);
        g_pack2[b*4096 + e] = make_float4(wxv*wzv, wyv*wzv, wzv, wwv);
    }
}

// ---------------- kernel D: main scan — 512 threads/CTA (8 elems/thread),
// 3-phase chunk design, packed f32x2, same-warp column grouping for na.
__global__ __launch_bounds__(512, 2)
void k_main(const float* __restrict__ zg, const float* __restrict__ zb,
            const float* __restrict__ nag, const float* __restrict__ nab,
            float* __restrict__ out, int NCH)
{
    extern __shared__ __align__(16) float SM[];
    float*  ztile = SM;                     // 2048
    float*  vtile = SM + 2048;              // 2048
    float*  qtile = SM + 4096;              // 2048
    float4* mom4  = (float4*)(SM + 6144);   // 32 steps * 16 warps * 3 = 1536 float4
    float4* scal4 = (float4*)(SM + 12288);  // 64 float4
    float*  na_s  = SM + 12544;             // 32*64 = 2048
    float*  cred  = SM + 14592;             // 16*8 = 128
    double* db    = (double*)(SM + 14720);  // 128 doubles = 256 floats
    // total 14976 floats = 59904 B

    int tid = threadIdx.x;
    int b = blockIdx.x / NCH, ch = blockIdx.x % NCH;
    int lane = tid & 31, w = tid >> 5;          // w: 0..15
    int p  = w*4 + (lane >> 3);                 // output column 0..63
    int d0 = (lane & 7) * 8;                    // row base (8 rows/thread)
    int L = NCH * CHUNK;
    size_t base = ((size_t)b*L + (size_t)ch*CHUNK) * 64;

    // preload whole chunk z/v/q tiles (one float4 per thread per array)
    {
        const float4* gz4 = (const float4*)(g_z + base);
        const float4* gv4 = (const float4*)(g_v + base);
        const float4* gq4 = (const float4*)(g_q + base);
        ((float4*)ztile)[tid] = gz4[tid];
        ((float4*)vtile)[tid] = gv4[tid];
        ((float4*)qtile)[tid] = gq4[tid];
    }
    // pass-1 constants -> registers (pairs over adjacent rows)
    ull wx2[4], wy2[4];
    {
        const float4* pk = &g_pack[b*4096];
        #pragma unroll
        for (int j = 0; j < 4; j++){
            float4 ta = pk[(d0 + 2*j    )*64 + p];
            float4 tb = pk[(d0 + 2*j + 1)*64 + p];
            wx2[j] = pack2(ta.x, tb.x);
            wy2[j] = pack2(ta.y, tb.y);
        }
    }
    float zpxv = 0.f, zpyv = 0.f;
    if (tid < 64){ zpxv = zg[tid]; zpyv = zb[tid] + g_Pz[b*64 + tid]; }
    float ngA = nag[lane], ngB = nag[lane+32];
    float nbA = nab[lane], nbB = nab[lane+32];

    // fused exclusive prefix over prior chunks' partials -> packed A2
    ull A2[4];
    float zc = 0.f;
    {
        float A[8];
        #pragma unroll
        for (int i = 0; i < 8; i++) A[i] = 0.f;
        for (int c2 = 0; c2 < ch; c2++){
            const float* gp = &g_part[(size_t)(b*NCH + c2) * 4160];
            #pragma unroll
            for (int i = 0; i < 8; i++) A[i] += gp[(d0 + i)*64 + p];
            if (tid < 64) zc += gp[4096 + tid];
        }
        #pragma unroll
        for (int j = 0; j < 4; j++) A2[j] = pack2(A[2*j], A[2*j+1]);
    }

    // per-CTA constants (one block reduce over 16 warps; makes tiles visible)
    float Cwx, Cwx2, Cwxwy, Cwy, Cwy2, Czpx2, Czpxzpy, Czpy2;
    {
        ull c0p = 0ull, c1p = 0ull, c2p = 0ull, c3p = 0ull, c4p = 0ull;
        #pragma unroll
        for (int j = 0; j < 4; j++){
            c0p = fadd2(c0p, wx2[j]);
            c1p = ffma2(wx2[j], wx2[j], c1p);
            c2p = ffma2(wx2[j], wy2[j], c2p);
            c3p = fadd2(c3p, wy2[j]);
            c4p = ffma2(wy2[j], wy2[j], c4p);
        }
        float cv[8];
        cv[0] = hsum2(c0p); cv[1] = hsum2(c1p); cv[2] = hsum2(c2p);
        cv[3] = hsum2(c3p); cv[4] = hsum2(c4p);
        cv[5] = zpxv*zpxv; cv[6] = zpxv*zpyv; cv[7] = zpyv*zpyv;  // 0 for tid>=64
        #pragma unroll
        for (int k = 0; k < 8; k++){
            #pragma unroll
            for (int o = 16; o; o >>= 1) cv[k] += __shfl_xor_sync(0xffffffffu, cv[k], o);
        }
        if (lane == 0){
            #pragma unroll
            for (int k = 0; k < 8; k++) cred[w*8 + k] = cv[k];
        }
        __syncthreads();                                        // sync 1
        float s[8];
        #pragma unroll
        for (int k = 0; k < 8; k++){
            float t = 0.f;
            #pragma unroll
            for (int w2 = 0; w2 < 16; w2++) t += cred[w2*8 + k];
            s[k] = t;
        }
        Cwx=s[0]; Cwx2=s[1]; Cwxwy=s[2]; Cwy=s[3]; Cwy2=s[4];
        Czpx2=s[5]; Czpxzpy=s[6]; Czpy2=s[7];
    }
    const float inv4096 = 1.f/4096.f, inv64 = 1.f/64.f;

    // ================= PASS 1: moments (packed), no syncs =================
    #pragma unroll 1
    for (int r = 0; r < CHUNK; r++){
        const ulonglong2* z2p = (const ulonglong2*)&ztile[r*64 + d0];
        float vv = vtile[r*64 + p];
        ull vv2 = pack2(vv, vv);
        ulonglong2 za = z2p[0], zbp = z2p[1];
        ull pS = 0ull, pS2 = 0ull, pU = 0ull, pU2 = 0ull, pUwx = 0ull, pUwy = 0ull;
        #pragma unroll
        for (int j = 0; j < 4; j++){
            ull zp = (j == 0) ? za.x : (j == 1) ? za.y : (j == 2) ? zbp.x : zbp.y;
            A2[j] = ffma2(zp, vv2, A2[j]);
            pS  = fadd2(pS, A2[j]);
            pS2 = ffma2(A2[j], A2[j], pS2);
            ull uu = fmul2(A2[j], wx2[j]);
            pU   = fadd2(pU, uu);
            pU2  = ffma2(uu, uu, pU2);
            pUwx = ffma2(uu, wx2[j], pUwx);
            pUwy = ffma2(uu, wy2[j], pUwy);
        }
        float sA = hsum2(pS),  sA2 = hsum2(pS2), sU = hsum2(pU);
        float sU2 = hsum2(pU2), sUwx = hsum2(pUwx), sUwy = hsum2(pUwy);

        float r6 = 0.f, r7 = 0.f, r8 = 0.f, r9 = 0.f, r10 = 0.f, r11 = 0.f;
        if (tid < 64){
            zc += ztile[r*64 + tid];
            float qv = qtile[r*64 + tid];
            float y = zc * zpxv;
            r6 = zc; r7 = zc*zc; r8 = y*y; r9 = y*zpyv; r10 = y*zpxv; r11 = qv*qv;
        }
        #pragma unroll
        for (int o = 16; o; o >>= 1){
            sA   += __shfl_xor_sync(0xffffffffu, sA, o);
            sA2  += __shfl_xor_sync(0xffffffffu, sA2, o);
            sU   += __shfl_xor_sync(0xffffffffu, sU, o);
            sU2  += __shfl_xor_sync(0xffffffffu, sU2, o);
            sUwx += __shfl_xor_sync(0xffffffffu, sUwx, o);
            sUwy += __shfl_xor_sync(0xffffffffu, sUwy, o);
        }
        if (w < 2){
            #pragma unroll
            for (int o = 16; o; o >>= 1){
                r6  += __shfl_xor_sync(0xffffffffu, r6, o);
                r7  += __shfl_xor_sync(0xffffffffu, r7, o);
                r8  += __shfl_xor_sync(0xffffffffu, r8, o);
                r9  += __shfl_xor_sync(0xffffffffu, r9, o);
                r10 += __shfl_xor_sync(0xffffffffu, r10, o);
                r11 += __shfl_xor_sync(0xffffffffu, r11, o);
            }
        }
        if (lane == 0){
            int mbase = (r*16 + w)*3;
            mom4[mbase + 0] = make_float4(sA, sA2, sU, sU2);
            mom4[mbase + 1] = make_float4(sUwx, sUwy, r6, r7);
            mom4[mbase + 2] = make_float4(r8, r9, r10, r11);
        }
    }
    __syncthreads();                                           // sync 2

    // ================= SCALAR PHASE: thread tid<32 owns step tid ==========
    if (tid < 32){
        int r = tid;
        float4 a0 = make_float4(0,0,0,0), a1 = a0, a2v = a0;
        #pragma unroll
        for (int w2 = 0; w2 < 16; w2++){
            int mbase = (r*16 + w2)*3;
            float4 t0 = mom4[mbase], t1 = mom4[mbase+1], t2 = mom4[mbase+2];
            a0.x += t0.x; a0.y += t0.y; a0.z += t0.z; a0.w += t0.w;
            a1.x += t1.x; a1.y += t1.y; a1.z += t1.z; a1.w += t1.w;
            a2v.x += t2.x; a2v.y += t2.y; a2v.z += t2.z; a2v.w += t2.w;
        }
        float aBar = a0.x * inv4096;
        float ivs  = rsqrtf(a0.y*inv4096 - aBar*aBar + LN_EPS);
        float c0   = aBar * ivs;
        float Sst  = ivs*a0.z - c0*Cwx + Cwy;
        float Sst2 = ivs*ivs*a0.w + 2.f*ivs*(a1.y - c0*a1.x)
                   + Cwy2 - 2.f*c0*Cwxwy + c0*c0*Cwx2;
        float mzv  = a1.z * inv64;
        float ivz  = rsqrtf(a1.w*inv64 - mzv*mzv + LN_EPS);
        float dd0  = mzv * ivz;
        float Szt2 = ivz*ivz*a2v.x + 2.f*ivz*(a2v.y - dd0*a2v.z)
                   + Czpy2 - 2.f*dd0*Czpxzpy + dd0*dd0*Czpx2;
        float zn   = fmaxf(sqrtf(Szt2), 1e-8f);
        float izn  = 1.f / zn;
        float mst  = Sst * inv4096;
        float mnam = mst * izn;
        float vnam = (Sst2*inv4096 - mst*mst) * izn * izn;
        float ivn  = rsqrtf(vnam + LN_EPS);
        float k1   = izn * ivn, k0 = -mnam * ivn;
        float srq  = 1.f / fmaxf(sqrtf(a2v.w), 1e-8f);
        float f1 = k1 * ivs, f2 = -f1 * aBar, f3 = k1;
        scal4[r*2 + 0] = make_float4(f1, f2, f3, k0);
        scal4[r*2 + 1] = make_float4(srq, mzv, ivz, 0.f);
    }
    __syncthreads();                                           // sync 3

    // ================= PASS 2: backward (packed, g_pack2), no syncs ========
    // t = f1*(A∘g1) + f2*g1 + f3*g2 + k0*wz + ww   (g1=wx*wz, g2=wy*wz)
    ull g1p[4], g2p[4], wzp[4], wwp[4];
    {
        const float4* pk2 = &g_pack2[b*4096];
        #pragma unroll
        for (int j = 0; j < 4; j++){
            float4 ta = pk2[(d0 + 2*j    )*64 + p];
            float4 tb = pk2[(d0 + 2*j + 1)*64 + p];
            g1p[j] = pack2(ta.x, tb.x);
            g2p[j] = pack2(ta.y, tb.y);
            wzp[j] = pack2(ta.z, tb.z);
            wwp[j] = pack2(ta.w, tb.w);
        }
    }
    float fsum = 0.f, fsq = 0.f;
    #pragma unroll 1
    for (int r = CHUNK - 1; r >= 0; r--){
        float4 s0 = scal4[r*2 + 0];
        ull f1p = pack2(s0.x, s0.x), f2p = pack2(s0.y, s0.y);
        ull f3p = pack2(s0.z, s0.z), k0p = pack2(s0.w, s0.w);
        const ulonglong2* z2p = (const ulonglong2*)&ztile[r*64 + d0];
        const ulonglong2* q2p = (const ulonglong2*)&qtile[r*64 + d0];
        ulonglong2 za = z2p[0], zbp = z2p[1];
        ulonglong2 qa = q2p[0], qbp = q2p[1];
        float vv = vtile[r*64 + p];
        ull nvv2 = pack2(-vv, -vv);
        ull pacc = 0ull;
        #pragma unroll
        for (int j = 0; j < 4; j++){
            ull zp = (j == 0) ? za.x : (j == 1) ? za.y : (j == 2) ? zbp.x : zbp.y;
            ull qp = (j == 0) ? qa.x : (j == 1) ? qa.y : (j == 2) ? qbp.x : qbp.y;
            ull pre = ffma2(k0p, wzp[j], wwp[j]);
            pre = ffma2(f3p, g2p[j], pre);
            pre = ffma2(f2p, g1p[j], pre);
            ull x = fmul2(A2[j], g1p[j]);
            ull t = ffma2(f1p, x, pre);
            pacc = ffma2(qp, t, pacc);
            A2[j] = ffma2(zp, nvv2, A2[j]);     // step back to A_{r-1}
        }
        float accn = hsum2(pacc);
        // reduce across the 8 lanes sharing this column (aligned groups of 8)
        accn += __shfl_down_sync(0xffffffffu, accn, 4);
        accn += __shfl_down_sync(0xffffffffu, accn, 2);
        accn += __shfl_down_sync(0xffffffffu, accn, 1);
        if ((lane & 7) == 0) na_s[r*64 + p] = accn;
        if (tid < 64){
            float4 s1 = scal4[r*2 + 1];
            float zt = (zc - s1.y)*s1.z*zpxv + zpyv;
            float rr = qtile[r*64 + tid] / fmaxf(zt, 1e-6f);
            fsum += rr; fsq = fmaf(rr, rr, fsq);
            zc -= ztile[r*64 + tid];
        }
    }
    if (tid < 64){ db[tid] = (double)fsum; db[64 + tid] = (double)fsq; }
    __syncthreads();                                           // sync 4

    // ================= EPILOGUE: warp w -> steps 2w, 2w+1 =================
    {
        #pragma unroll
        for (int rr = 0; rr < 2; rr++){
            int r = w*2 + rr;
            float srq = scal4[r*2 + 1].x;
            const float* np = &na_s[r*64];
            float nvA = np[lane] * srq;
            float nvB = np[lane + 32] * srq;
            float s1 = nvA + nvB, s2 = nvA*nvA + nvB*nvB;
            #pragma unroll
            for (int o = 16; o; o >>= 1){
                s1 += __shfl_xor_sync(0xffffffffu, s1, o);
                s2 += __shfl_xor_sync(0xffffffffu, s2, o);
            }
            float mn = s1 * inv64;
            float iv = rsqrtf(s2*inv64 - mn*mn + LN_EPS);
            float* op = out + base + (size_t)r*64;
            op[lane]      = (nvA - mn)*iv*ngA + nbA;
            op[lane + 32] = (nvB - mn)*iv*ngB + nbB;
        }
    }
    if (tid == 0){
        double a = 0.0, c = 0.0;
        for (int i = 0; i < 64; i++){ a += db[i]; c += db[64 + i]; }
        atomicAdd(&g_acc[0], a);
        atomicAdd(&g_acc[1], c);
    }
}

// ---------------- kernel E: finalize std ----------------
__global__ void k_std(float* out, int n, int outpos)
{
    double mean = g_acc[0] / (double)n;
    double var  = (g_acc[1] - g_acc[0]*mean) / (double)(n - 1);
    out[outpos] = (float)sqrt(var);
}

// ---------------- launch ----------------
extern "C" void kernel_launch(void* const* d_in, const int* in_sizes, int n_in,
                              void* d_out, int out_size)
{
    const int*   uid   = (const int*)  d_in[0];
    const float* X     = (const float*)d_in[1];
    const float* Pm    = (const float*)d_in[2];
    const float* Sm    = (const float*)d_in[3];
    const float* Wq    = (const float*)d_in[4];
    const float* bq    = (const float*)d_in[5];
    const float* Wk    = (const float*)d_in[6];
    const float* bk    = (const float*)d_in[7];
    const float* Wv    = (const float*)d_in[8];
    const float* bv    = (const float*)d_in[9];
    const float* zg    = (const float*)d_in[10];
    const float* zb    = (const float*)d_in[11];
    const float* sg    = (const float*)d_in[12];
    const float* sb    = (const float*)d_in[13];
    const float* ng    = (const float*)d_in[14];
    const float* nb    = (const float*)d_in[15];
    const float* nag   = (const float*)d_in[16];
    const float* nab   = (const float*)d_in[17];
    const float* pzbuf = (const float*)d_in[18];
    const float* psbuf = (const float*)d_in[19];
    float* out = (float*)d_out;

    int B   = in_sizes[0];
    int L   = in_sizes[1] / (B * 64);
    int NCH = L / CHUNK;
    int LP  = in_sizes[2] / (B * 64);
    int NPH = B * NCH;

    size_t smMain = (size_t)14976 * 4;   // 59904 B dynamic
    cudaFuncSetAttribute(k_main, cudaFuncAttributeMaxDynamicSharedMemorySize, (int)smMain);

    k_front<<<B + 2*NPH, 256>>>(uid, X, Pm, Sm, Wq, bq, Wk, bk, Wv, bv,
                                zg, zb, sg, sb, ng, nb, pzbuf, psbuf, NCH, LP, B);
    k_main<<<NPH, 512, smMain>>>(zg, zb, nag, nab, out, NCH);
    k_std<<<1, 1>>>(out, B*L*64, out_size - 1);
}

// round 13
// speedup vs baseline: 1.3973x; 1.3973x over previous
#include <cuda_runtime.h>
#include <math.h>

#define EPS 1e-8f
#define LN_EPS 1e-5f
#define CHUNK 32

typedef unsigned long long ull;

// ---------------- packed f32x2 helpers (sm_103a) ----------------
__device__ __forceinline__ ull pack2(float lo, float hi){
    ull r; asm("mov.b64 %0, {%1,%2};" : "=l"(r) : "f"(lo), "f"(hi)); return r;
}
__device__ __forceinline__ void unpack2(ull v, float &lo, float &hi){
    asm("mov.b64 {%0,%1}, %2;" : "=f"(lo), "=f"(hi) : "l"(v));
}
__device__ __forceinline__ ull ffma2(ull a, ull b, ull c){
    ull d; asm("fma.rn.f32x2 %0, %1, %2, %3;" : "=l"(d) : "l"(a), "l"(b), "l"(c)); return d;
}
__device__ __forceinline__ ull fmul2(ull a, ull b){
    ull d; asm("mul.rn.f32x2 %0, %1, %2;" : "=l"(d) : "l"(a), "l"(b)); return d;
}
__device__ __forceinline__ ull fadd2(ull a, ull b){
    ull d; asm("add.rn.f32x2 %0, %1, %2;" : "=l"(d) : "l"(a), "l"(b)); return d;
}
__device__ __forceinline__ float hsum2(ull v){ float lo, hi; unpack2(v, lo, hi); return lo + hi; }

// ---------------- scratch (static __device__, no allocs) ----------------
__device__ __align__(16) float  g_q[16*512*64];
__device__ __align__(16) float  g_z[16*512*64];
__device__ __align__(16) float  g_v[16*512*64];
__device__ __align__(16) float  g_part[16*16*4160];
__device__ float4 g_pack[16*4096];      // {wx=sg, wy=sb+Ps_ln, wz=ng, ww=nb+Mprev_ln}
__device__ float  g_Pz[16*64];          // P_z_ln last step per batch
__device__ double g_acc[2];             // sum, sumsq for std

__device__ __forceinline__ float eluf(float x){ return x > 0.f ? x : (expf(x) - 1.f); }

// one-sync block reduce for 512 threads (16 warps). Results broadcast to ALL
// threads in out[]. red: >= 16*N floats.
template<int N>
__device__ __forceinline__ void block_reduce_c(const float* v, float* red, float* out){
    int lane = threadIdx.x & 31, w = threadIdx.x >> 5;
    #pragma unroll
    for (int i = 0; i < N; i++){
        float x = v[i];
        #pragma unroll
        for (int o = 16; o; o >>= 1) x += __shfl_xor_sync(0xffffffffu, x, o);
        if (lane == 0) red[w*N + i] = x;
    }
    __syncthreads();
    #pragma unroll
    for (int i = 0; i < N; i++){
        float s = 0.f;
        #pragma unroll
        for (int ww2 = 0; ww2 < 16; ww2++) s += red[ww2*N + i];
        out[i] = s;
    }
}

// ---------------- fused front kernel (512 threads/CTA):
//  blocks [0,B)        : prompt/history precompute
//  blocks [B, B+B*NCH) : q/z/v GEMVs + per-chunk outer-product partials
__global__ __launch_bounds__(512, 2)
void k_front(const int* uid, const float* X, const float* Pm, const float* Sm,
             const float* Wq, const float* bq, const float* Wk, const float* bk,
             const float* Wv, const float* bv,
             const float* zg, const float* zb, const float* sg, const float* sb,
             const float* ng, const float* nb,
             const float* pzbuf, const float* psbuf, int NCH, int LP, int B)
{
    __shared__ __align__(16) float SBUF[11424];
    int tid = threadIdx.x;
    int bi = blockIdx.x;

    if (bi >= B){
        // ---------------- phase1 branch (packed f32x2, 512 threads) --------
        float* xsT  = SBUF;            // 64*36 transposed X chunk
        float* zbuf = SBUF + 2304;     // 32*64
        float* vbuf = SBUF + 4352;     // 32*64

        int pid = bi - B;
        int b = pid / NCH, ch = pid % NCH;
        int L = NCH * CHUNK;
        size_t xbase = ((size_t)b*L + (size_t)ch*CHUNK) * 64;

        #pragma unroll
        for (int i = 0; i < 4; i++){
            int e = tid + i*512;
            int l = e >> 6, k = e & 63;
            xsT[k*36 + l] = X[xbase + e];
        }
        __syncthreads();

        // GEMV: 384 threads = (dt: q/z/v) x (col 0..63) x (16-row half)
        if (tid < 384){
            int dt = tid >> 7;              // 0=q, 1=z, 2=v
            int sub = tid & 127;
            int col = sub & 63;
            int half = sub >> 6;            // rows half*16 .. half*16+15
            const float* W = (dt == 0) ? Wq : ((dt == 1) ? Wk : Wv);
            float bb = (dt == 0) ? bq[col] : ((dt == 1) ? bk[col] : bv[col]);
            ull bb2 = pack2(bb, bb);
            ull acc2[8];
            #pragma unroll
            for (int j = 0; j < 8; j++) acc2[j] = bb2;
            #pragma unroll 4
            for (int k = 0; k < 64; k++){
                float w = W[k*64 + col];
                ull wp = pack2(w, w);
                const ulonglong2* xr = (const ulonglong2*)&xsT[k*36 + half*16];
                ulonglong2 x0 = xr[0], x1 = xr[1], x2 = xr[2], x3 = xr[3];
                acc2[0] = ffma2(x0.x, wp, acc2[0]); acc2[1] = ffma2(x0.y, wp, acc2[1]);
                acc2[2] = ffma2(x1.x, wp, acc2[2]); acc2[3] = ffma2(x1.y, wp, acc2[3]);
                acc2[4] = ffma2(x2.x, wp, acc2[4]); acc2[5] = ffma2(x2.y, wp, acc2[5]);
                acc2[6] = ffma2(x3.x, wp, acc2[6]); acc2[7] = ffma2(x3.y, wp, acc2[7]);
            }
            int row0 = half*16;
            if (dt == 0){
                #pragma unroll
                for (int j = 0; j < 8; j++){
                    float a, b2; unpack2(acc2[j], a, b2);
                    g_q[xbase + (row0 + 2*j    )*64 + col] = eluf(a);
                    g_q[xbase + (row0 + 2*j + 1)*64 + col] = eluf(b2);
                }
            } else if (dt == 1){
                #pragma unroll
                for (int j = 0; j < 8; j++){
                    float a, b2; unpack2(acc2[j], a, b2);
                    float za = eluf(a), zb2v = eluf(b2);
                    int r0 = row0 + 2*j;
                    zbuf[r0*64 + col] = za;        g_z[xbase + r0*64 + col] = za;
                    zbuf[(r0+1)*64 + col] = zb2v;  g_z[xbase + (r0+1)*64 + col] = zb2v;
                }
            } else {
                #pragma unroll
                for (int j = 0; j < 8; j++){
                    float a, b2; unpack2(acc2[j], a, b2);
                    int r0 = row0 + 2*j;
                    vbuf[r0*64 + col] = a;    g_v[xbase + r0*64 + col] = a;
                    vbuf[(r0+1)*64 + col] = b2; g_v[xbase + (r0+1)*64 + col] = b2;
                }
            }
        }
        __syncthreads();

        // outer products: 512 threads, 8 elems each
        int p = tid & 63, d0 = (tid >> 6) * 8;
        ull acc2o[4];
        #pragma unroll
        for (int j = 0; j < 4; j++) acc2o[j] = 0ull;
        #pragma unroll 4
        for (int l = 0; l < 32; l++){
            float vv = vbuf[l*64 + p];
            ull vvp = pack2(vv, vv);
            const ulonglong2* zb2p = (const ulonglong2*)&zbuf[l*64 + d0];
            ulonglong2 zz0 = zb2p[0], zz1 = zb2p[1];
            acc2o[0] = ffma2(zz0.x, vvp, acc2o[0]);
            acc2o[1] = ffma2(zz0.y, vvp, acc2o[1]);
            acc2o[2] = ffma2(zz1.x, vvp, acc2o[2]);
            acc2o[3] = ffma2(zz1.y, vvp, acc2o[3]);
        }
        size_t o = (size_t)(b*NCH + ch) * 4160;
        #pragma unroll
        for (int j = 0; j < 4; j++){
            float a, b2; unpack2(acc2o[j], a, b2);
            g_part[o + (d0 + 2*j  )*64 + p] = a;
            g_part[o + (d0 + 2*j+1)*64 + p] = b2;
        }
        if (tid < 64){
            float zs = 0.f;
            #pragma unroll 4
            for (int l = 0; l < 32; l++) zs += zbuf[l*64 + tid];
            g_part[o + 4096 + tid] = zs;
        }
        return;
    }

    // ---------------- prompt branch (blocks [0,B), 512 threads) ----------
    float* xsA  = SBUF;          float* xsB  = SBUF + 512;
    float* zbA  = SBUF + 1024;   float* zbB  = SBUF + 1536;
    float* vbA  = SBUF + 2048;   float* vbB  = SBUF + 2560;
    float* bufA = SBUF + 3072;   float* bufB = SBUF + 7168;
    float* zl   = SBUF + 11264;  // 64
    float* redA = SBUF + 11328;  // 32
    float* redB = SBUF + 11360;  // 32

    int b = bi;
    int p = tid & 63, d0 = (tid >> 6) * 16;

    if (b == 0 && tid == 0){ g_acc[0] = 0.0; g_acc[1] = 0.0; }

    for (int i = tid; i < 512; i += 512){ xsA[i] = 0.f; xsB[i] = 0.f; }
    __syncthreads();
    for (int i = tid; i < LP*64; i += 512){
        xsA[i] = Pm[b*LP*64 + i];
        xsB[i] = Sm[b*LP*64 + i];
    }
    __syncthreads();

    if (tid < 256){
        int pass = tid >> 7, dt = (tid >> 6) & 1, col = tid & 63;
        const float* xp = pass ? xsB : xsA;
        float* zp = pass ? zbB : zbA;
        float* vp = pass ? vbB : vbA;
        const float* W  = dt ? Wv : Wk;
        float bb = dt ? bv[col] : bk[col];
        float acc8[8];
        #pragma unroll
        for (int l = 0; l < 8; l++) acc8[l] = bb;
        #pragma unroll 4
        for (int k = 0; k < 64; k++){
            float w = W[k*64 + col];
            #pragma unroll
            for (int l = 0; l < 8; l++) acc8[l] += xp[l*64 + k] * w;
        }
        if (dt == 0){
            #pragma unroll
            for (int l = 0; l < 8; l++) zp[l*64 + col] = eluf(acc8[l]);
        } else {
            #pragma unroll
            for (int l = 0; l < 8; l++) vp[l*64 + col] = acc8[l];
        }
    }
    __syncthreads();

    float accP[16], accS[16];
    #pragma unroll
    for (int i = 0; i < 16; i++){ accP[i] = 0.f; accS[i] = 0.f; }
    if (tid < 256){
        for (int l = 0; l < LP; l++){
            float vvP = vbA[l*64 + p], vvS = vbB[l*64 + p];
            #pragma unroll
            for (int i = 0; i < 16; i++){
                accP[i] += zbA[l*64 + d0 + i] * vvP;
                accS[i] += zbB[l*64 + d0 + i] * vvS;
            }
        }
    }
    float zsP = 0.f, zsS = 0.f;
    if (tid < 64){
        for (int l = 0; l < LP; l++){ zsP += zbA[l*64 + tid]; zsS += zbB[l*64 + tid]; }
    }

    float rv[2], out2[2];
    rv[0] = (tid < 64) ? zsP : 0.f; rv[1] = (tid < 64) ? zsP*zsP : 0.f;
    block_reduce_c<2>(rv, redA, out2);
    {
        float mz = out2[0]*(1.f/64.f);
        float ivz = rsqrtf(out2[1]*(1.f/64.f) - mz*mz + LN_EPS);
        if (tid < 64) g_Pz[b*64 + tid] = (zsP - mz)*ivz*zg[tid] + zb[tid];
    }
    rv[0] = (tid < 64) ? zsS : 0.f; rv[1] = (tid < 64) ? zsS*zsS : 0.f;
    block_reduce_c<2>(rv, redB, out2);
    {
        float mz = out2[0]*(1.f/64.f);
        float ivz = rsqrtf(out2[1]*(1.f/64.f) - mz*mz + LN_EPS);
        if (tid < 64) zl[tid] = (zsS - mz)*ivz*zg[tid] + zb[tid];
    }
    float sv[2];
    sv[0] = 0.f; sv[1] = 0.f;
    #pragma unroll
    for (int i = 0; i < 16; i++){ sv[0] += accP[i]; sv[1] += accP[i]*accP[i]; }
    block_reduce_c<2>(sv, redA, out2);
    if (tid < 256){
        float ms = out2[0]*(1.f/4096.f);
        float ivs = rsqrtf(out2[1]*(1.f/4096.f) - ms*ms + LN_EPS);
        #pragma unroll
        for (int i = 0; i < 16; i++){
            int e = (d0 + i)*64 + p;
            bufA[e] = (accP[i] - ms)*ivs*sg[e] + sb[e];
        }
    }
    sv[0] = 0.f; sv[1] = 0.f;
    #pragma unroll
    for (int i = 0; i < 16; i++){ sv[0] += accS[i]; sv[1] += accS[i]*accS[i]; }
    block_reduce_c<2>(sv, redB, out2);
    if (tid < 256){
        float ms = out2[0]*(1.f/4096.f);
        float ivs = rsqrtf(out2[1]*(1.f/4096.f) - ms*ms + LN_EPS);
        #pragma unroll
        for (int i = 0; i < 16; i++){
            int e = (d0 + i)*64 + p;
            bufB[e] = (accS[i] - ms)*ivs*sg[e] + sb[e];
        }
    }
    __syncthreads();

    int u = uid[b];
    float pzv = 0.f;
    if (tid < 64) pzv = pzbuf[(size_t)u*64 + tid] + zl[tid];
    float rv1[1], out1[1];
    rv1[0] = (tid < 64) ? pzv*pzv : 0.f;
    block_reduce_c<1>(rv1, redA, out1);
    float ipn = 1.f / (fmaxf(sqrtf(out1[0]), 1e-8f) + EPS);

    float pn8[8];
    sv[0] = 0.f; sv[1] = 0.f;
    #pragma unroll
    for (int k2 = 0; k2 < 8; k2++){
        int e = tid + k2*512;
        float pv = (psbuf[(size_t)u*4096 + e] + bufB[e]) * ipn;
        pn8[k2] = pv; sv[0] += pv; sv[1] += pv*pv;
    }
    block_reduce_c<2>(sv, redB, out2);
    float mp = out2[0]*(1.f/4096.f);
    float ivp = rsqrtf(out2[1]*(1.f/4096.f) - mp*mp + LN_EPS);
    #pragma unroll
    for (int k2 = 0; k2 < 8; k2++){
        int e = tid + k2*512;
        float M = (pn8[k2] - mp)*ivp*ng[e] + nb[e];
        g_pack[b*4096 + e] = make_float4(sg[e], sb[e] + bufA[e], ng[e], nb[e] + M);
    }
}

// ---------------- kernel D: main scan — 3-phase chunk design, packed f32x2
// (R11 version verbatim: 256 threads, 128 regs, no spills).
__global__ __launch_bounds__(256, 2)
void k_main(const float* __restrict__ zg, const float* __restrict__ zb,
            const float* __restrict__ nag, const float* __restrict__ nab,
            float* __restrict__ out, int NCH)
{
    extern __shared__ __align__(16) float SM[];
    float*  ztile = SM;                     // 2048
    float*  vtile = SM + 2048;              // 2048
    float*  qtile = SM + 4096;              // 2048
    float4* mom4  = (float4*)(SM + 6144);   // 32*8*3 float4 = 3072 floats
    float4* scal4 = (float4*)(SM + 9216);   // 64 float4 = 256 floats
    float*  na_s  = SM + 9472;              // 8192
    float*  cred  = SM + 17664;             // 64
    double* db    = (double*)(SM + 17728);  // 128 doubles = 256 floats

    int tid = threadIdx.x;
    int b = blockIdx.x / NCH, ch = blockIdx.x % NCH;
    int lane = tid & 31, w = tid >> 5;
    int p = tid & 63, d0 = (tid >> 6) * 16;
    int L = NCH * CHUNK;
    size_t base = ((size_t)b*L + (size_t)ch*CHUNK) * 64;

    // preload whole chunk z/v/q tiles (float4)
    {
        const float4* gz4 = (const float4*)(g_z + base);
        const float4* gv4 = (const float4*)(g_v + base);
        const float4* gq4 = (const float4*)(g_q + base);
        float4* zt4 = (float4*)ztile; float4* vt4 = (float4*)vtile; float4* qt4 = (float4*)qtile;
        #pragma unroll
        for (int i = 0; i < 2; i++){
            int e = tid + i*256;
            zt4[e] = gz4[e]; vt4[e] = gv4[e]; qt4[e] = gq4[e];
        }
    }
    // packed constants -> registers (pairs over adjacent i)
    ull wx2[8], wy2[8], wz2[8], ww2[8];
    {
        const float4* pk = &g_pack[b*4096];
        #pragma unroll
        for (int j = 0; j < 8; j++){
            float4 ta = pk[(d0 + 2*j    )*64 + p];
            float4 tb = pk[(d0 + 2*j + 1)*64 + p];
            wx2[j] = pack2(ta.x, tb.x);
            wy2[j] = pack2(ta.y, tb.y);
            wz2[j] = pack2(ta.z, tb.z);
            ww2[j] = pack2(ta.w, tb.w);
        }
    }
    float zpxv = 0.f, zpyv = 0.f;
    if (tid < 64){ zpxv = zg[tid]; zpyv = zb[tid] + g_Pz[b*64 + tid]; }
    float ngA = nag[lane], ngB = nag[lane+32];
    float nbA = nab[lane], nbB = nab[lane+32];

    // fused exclusive prefix over prior chunks' partials -> packed A2
    ull A2[8];
    float zc = 0.f;
    {
        float A[16];
        #pragma unroll
        for (int i = 0; i < 16; i++) A[i] = 0.f;
        for (int c2 = 0; c2 < ch; c2++){
            const float* gp = &g_part[(size_t)(b*NCH + c2) * 4160];
            #pragma unroll
            for (int i = 0; i < 16; i++) A[i] += gp[(d0 + i)*64 + p];
            if (tid < 64) zc += gp[4096 + tid];
        }
        #pragma unroll
        for (int j = 0; j < 8; j++) A2[j] = pack2(A[2*j], A[2*j+1]);
    }

    // per-CTA constants (packed sums; one block reduce; makes tiles visible)
    float Cwx, Cwx2, Cwxwy, Cwy, Cwy2, Czpx2, Czpxzpy, Czpy2;
    {
        ull c0p = 0ull, c1p = 0ull, c2p = 0ull, c3p = 0ull, c4p = 0ull;
        #pragma unroll
        for (int j = 0; j < 8; j++){
            c0p = fadd2(c0p, wx2[j]);
            c1p = ffma2(wx2[j], wx2[j], c1p);
            c2p = ffma2(wx2[j], wy2[j], c2p);
            c3p = fadd2(c3p, wy2[j]);
            c4p = ffma2(wy2[j], wy2[j], c4p);
        }
        float cv[8];
        cv[0] = hsum2(c0p); cv[1] = hsum2(c1p); cv[2] = hsum2(c2p);
        cv[3] = hsum2(c3p); cv[4] = hsum2(c4p);
        cv[5] = zpxv*zpxv; cv[6] = zpxv*zpyv; cv[7] = zpyv*zpyv;  // 0 for tid>=64
        #pragma unroll
        for (int k = 0; k < 8; k++){
            #pragma unroll
            for (int o = 16; o; o >>= 1) cv[k] += __shfl_xor_sync(0xffffffffu, cv[k], o);
        }
        if (lane == 0){
            #pragma unroll
            for (int k = 0; k < 8; k++) cred[w*8 + k] = cv[k];
        }
        __syncthreads();                                        // sync 1
        float s[8];
        #pragma unroll
        for (int k = 0; k < 8; k++){
            float t = 0.f;
            #pragma unroll
            for (int w2 = 0; w2 < 8; w2++) t += cred[w2*8 + k];
            s[k] = t;
        }
        Cwx=s[0]; Cwx2=s[1]; Cwxwy=s[2]; Cwy=s[3]; Cwy2=s[4];
        Czpx2=s[5]; Czpxzpy=s[6]; Czpy2=s[7];
    }
    const float inv4096 = 1.f/4096.f, inv64 = 1.f/64.f;

    // ================= PASS 1: moments (packed), no syncs =================
    #pragma unroll 1
    for (int r = 0; r < CHUNK; r++){
        const ulonglong2* z2p = (const ulonglong2*)&ztile[r*64 + d0];
        float vv = vtile[r*64 + p];
        ull vv2 = pack2(vv, vv);
        ull pS = 0ull, pS2 = 0ull, pU = 0ull, pU2 = 0ull, pUwx = 0ull, pUwy = 0ull;
        #pragma unroll
        for (int j4 = 0; j4 < 4; j4++){
            ulonglong2 zz = z2p[j4];
            #pragma unroll
            for (int c = 0; c < 2; c++){
                int j = j4*2 + c;
                ull zp = c ? zz.y : zz.x;
                A2[j] = ffma2(zp, vv2, A2[j]);
                pS  = fadd2(pS, A2[j]);
                pS2 = ffma2(A2[j], A2[j], pS2);
                ull uu = fmul2(A2[j], wx2[j]);
                pU   = fadd2(pU, uu);
                pU2  = ffma2(uu, uu, pU2);
                pUwx = ffma2(uu, wx2[j], pUwx);
                pUwy = ffma2(uu, wy2[j], pUwy);
            }
        }
        float sA = hsum2(pS),  sA2 = hsum2(pS2), sU = hsum2(pU);
        float sU2 = hsum2(pU2), sUwx = hsum2(pUwx), sUwy = hsum2(pUwy);

        float r6 = 0.f, r7 = 0.f, r8 = 0.f, r9 = 0.f, r10 = 0.f, r11 = 0.f;
        if (tid < 64){
            zc += ztile[r*64 + tid];
            float qv = qtile[r*64 + tid];
            float y = zc * zpxv;
            r6 = zc; r7 = zc*zc; r8 = y*y; r9 = y*zpyv; r10 = y*zpxv; r11 = qv*qv;
        }
        #pragma unroll
        for (int o = 16; o; o >>= 1){
            sA   += __shfl_xor_sync(0xffffffffu, sA, o);
            sA2  += __shfl_xor_sync(0xffffffffu, sA2, o);
            sU   += __shfl_xor_sync(0xffffffffu, sU, o);
            sU2  += __shfl_xor_sync(0xffffffffu, sU2, o);
            sUwx += __shfl_xor_sync(0xffffffffu, sUwx, o);
            sUwy += __shfl_xor_sync(0xffffffffu, sUwy, o);
        }
        if (w < 2){
            #pragma unroll
            for (int o = 16; o; o >>= 1){
                r6  += __shfl_xor_sync(0xffffffffu, r6, o);
                r7  += __shfl_xor_sync(0xffffffffu, r7, o);
                r8  += __shfl_xor_sync(0xffffffffu, r8, o);
                r9  += __shfl_xor_sync(0xffffffffu, r9, o);
                r10 += __shfl_xor_sync(0xffffffffu, r10, o);
                r11 += __shfl_xor_sync(0xffffffffu, r11, o);
            }
        }
        if (lane == 0){
            int mbase = (r*8 + w)*3;
            mom4[mbase + 0] = make_float4(sA, sA2, sU, sU2);
            mom4[mbase + 1] = make_float4(sUwx, sUwy, r6, r7);
            mom4[mbase + 2] = make_float4(r8, r9, r10, r11);
        }
    }
    __syncthreads();                                           // sync 2

    // ================= SCALAR PHASE: thread tid<32 owns step tid ==========
    if (tid < 32){
        int r = tid;
        float4 a0 = make_float4(0,0,0,0), a1 = a0, a2v = a0;
        #pragma unroll
        for (int w2 = 0; w2 < 8; w2++){
            int mbase = (r*8 + w2)*3;
            float4 t0 = mom4[mbase], t1 = mom4[mbase+1], t2 = mom4[mbase+2];
            a0.x += t0.x; a0.y += t0.y; a0.z += t0.z; a0.w += t0.w;
            a1.x += t1.x; a1.y += t1.y; a1.z += t1.z; a1.w += t1.w;
            a2v.x += t2.x; a2v.y += t2.y; a2v.z += t2.z; a2v.w += t2.w;
        }
        float aBar = a0.x * inv4096;
        float ivs  = rsqrtf(a0.y*inv4096 - aBar*aBar + LN_EPS);
        float c0   = aBar * ivs;
        float Sst  = ivs*a0.z - c0*Cwx + Cwy;
        float Sst2 = ivs*ivs*a0.w + 2.f*ivs*(a1.y - c0*a1.x)
                   + Cwy2 - 2.f*c0*Cwxwy + c0*c0*Cwx2;
        float mzv  = a1.z * inv64;
        float ivz  = rsqrtf(a1.w*inv64 - mzv*mzv + LN_EPS);
        float dd0  = mzv * ivz;
        float Szt2 = ivz*ivz*a2v.x + 2.f*ivz*(a2v.y - dd0*a2v.z)
                   + Czpy2 - 2.f*dd0*Czpxzpy + dd0*dd0*Czpx2;
        float zn   = fmaxf(sqrtf(Szt2), 1e-8f);
        float izn  = 1.f / zn;
        float mst  = Sst * inv4096;
        float mnam = mst * izn;
        float vnam = (Sst2*inv4096 - mst*mst) * izn * izn;
        float ivn  = rsqrtf(vnam + LN_EPS);
        float k1   = izn * ivn, k0 = -mnam * ivn;
        float srq  = 1.f / fmaxf(sqrtf(a2v.w), 1e-8f);
        float f1 = k1 * ivs, f2 = -f1 * aBar, f3 = k1;
        scal4[r*2 + 0] = make_float4(f1, f2, f3, k0);
        scal4[r*2 + 1] = make_float4(srq, mzv, ivz, 0.f);
    }
    __syncthreads();                                           // sync 3

    // ================= PASS 2: backward (packed), no syncs, no FP64 =======
    float fsum = 0.f, fsq = 0.f;
    #pragma unroll 1
    for (int r = CHUNK - 1; r >= 0; r--){
        float4 s0 = scal4[r*2 + 0];
        ull f1p = pack2(s0.x, s0.x), f2p = pack2(s0.y, s0.y);
        ull f3p = pack2(s0.z, s0.z), k0p = pack2(s0.w, s0.w);
        const ulonglong2* z2p = (const ulonglong2*)&ztile[r*64 + d0];
        const ulonglong2* q2p = (const ulonglong2*)&qtile[r*64 + d0];
        float vv = vtile[r*64 + p];
        ull nvv2 = pack2(-vv, -vv);
        ull pacc = 0ull;
        #pragma unroll
        for (int j4 = 0; j4 < 4; j4++){
            ulonglong2 zz = z2p[j4];
            ulonglong2 qq = q2p[j4];
            #pragma unroll
            for (int c = 0; c < 2; c++){
                int j = j4*2 + c;
                ull zp = c ? zz.y : zz.x;
                ull qp = c ? qq.y : qq.x;
                ull uu = fmul2(A2[j], wx2[j]);
                ull aa = ffma2(f1p, uu, k0p);
                aa = ffma2(f2p, wx2[j], aa);
                aa = ffma2(f3p, wy2[j], aa);
                ull t = ffma2(aa, wz2[j], ww2[j]);
                pacc = ffma2(qp, t, pacc);
                A2[j] = ffma2(zp, nvv2, A2[j]);    // step back to A_{r-1}
            }
        }
        na_s[r*256 + tid] = hsum2(pacc);
        if (tid < 64){
            float4 s1 = scal4[r*2 + 1];
            float zt = (zc - s1.y)*s1.z*zpxv + zpyv;
            float rr = qtile[r*64 + tid] / fmaxf(zt, 1e-6f);
            fsum += rr; fsq = fmaf(rr, rr, fsq);
            zc -= ztile[r*64 + tid];
        }
    }
    if (tid < 64){ db[tid] = (double)fsum; db[64 + tid] = (double)fsq; }
    __syncthreads();                                           // sync 4

    // ================= EPILOGUE: warp w -> steps w*4 .. w*4+3 ==============
    {
        #pragma unroll
        for (int rr = 0; rr < 4; rr++){
            int r = w*4 + rr;
            float srq = scal4[r*2 + 1].x;
            const float* np = &na_s[r*256];
            float nvA = (np[lane] + np[lane+64] + np[lane+128] + np[lane+192]) * srq;
            float nvB = (np[lane+32] + np[lane+96] + np[lane+160] + np[lane+224]) * srq;
            float s1 = nvA + nvB, s2 = nvA*nvA + nvB*nvB;
            #pragma unroll
            for (int o = 16; o; o >>= 1){
                s1 += __shfl_xor_sync(0xffffffffu, s1, o);
                s2 += __shfl_xor_sync(0xffffffffu, s2, o);
            }
            float mn = s1 * inv64;
            float iv = rsqrtf(s2*inv64 - mn*mn + LN_EPS);
            float* op = out + base + (size_t)r*64;
            op[lane]      = (nvA - mn)*iv*ngA + nbA;
            op[lane + 32] = (nvB - mn)*iv*ngB + nbB;
        }
    }
    if (tid == 0){
        double a = 0.0, c = 0.0;
        for (int i = 0; i < 64; i++){ a += db[i]; c += db[64 + i]; }
        atomicAdd(&g_acc[0], a);
        atomicAdd(&g_acc[1], c);
    }
}

// ---------------- kernel E: finalize std ----------------
__global__ void k_std(float* out, int n, int outpos)
{
    double mean = g_acc[0] / (double)n;
    double var  = (g_acc[1] - g_acc[0]*mean) / (double)(n - 1);
    out[outpos] = (float)sqrt(var);
}

// ---------------- launch ----------------
extern "C" void kernel_launch(void* const* d_in, const int* in_sizes, int n_in,
                              void* d_out, int out_size)
{
    const int*   uid   = (const int*)  d_in[0];
    const float* X     = (const float*)d_in[1];
    const float* Pm    = (const float*)d_in[2];
    const float* Sm    = (const float*)d_in[3];
    const float* Wq    = (const float*)d_in[4];
    const float* bq    = (const float*)d_in[5];
    const float* Wk    = (const float*)d_in[6];
    const float* bk    = (const float*)d_in[7];
    const float* Wv    = (const float*)d_in[8];
    const float* bv    = (const float*)d_in[9];
    const float* zg    = (const float*)d_in[10];
    const float* zb    = (const float*)d_in[11];
    const float* sg    = (const float*)d_in[12];
    const float* sb    = (const float*)d_in[13];
    const float* ng    = (const float*)d_in[14];
    const float* nb    = (const float*)d_in[15];
    const float* nag   = (const float*)d_in[16];
    const float* nab   = (const float*)d_in[17];
    const float* pzbuf = (const float*)d_in[18];
    const float* psbuf = (const float*)d_in[19];
    float* out = (float*)d_out;

    int B   = in_sizes[0];
    int L   = in_sizes[1] / (B * 64);
    int NCH = L / CHUNK;
    int LP  = in_sizes[2] / (B * 64);
    int NPH = B * NCH;

    size_t smMain = (size_t)(17728 + 256) * 4;   // ~72 KB dynamic
    cudaFuncSetAttribute(k_main, cudaFuncAttributeMaxDynamicSharedMemorySize, (int)smMain);

    k_front<<<B + NPH, 512>>>(uid, X, Pm, Sm, Wq, bq, Wk, bk, Wv, bv,
                              zg, zb, sg, sb, ng, nb, pzbuf, psbuf, NCH, LP, B);
    k_main<<<NPH, 256, smMain>>>(zg, zb, nag, nab, out, NCH);
    k_std<<<1, 1>>>(out, B*L*64, out_size - 1);
}

// round 14
// speedup vs baseline: 1.4322x; 1.0249x over previous
#include <cuda_runtime.h>
#include <math.h>

#define EPS 1e-8f
#define LN_EPS 1e-5f
#define CHUNK 32

typedef unsigned long long ull;

// ---------------- packed f32x2 helpers (sm_103a) ----------------
__device__ __forceinline__ ull pack2(float lo, float hi){
    ull r; asm("mov.b64 %0, {%1,%2};" : "=l"(r) : "f"(lo), "f"(hi)); return r;
}
__device__ __forceinline__ void unpack2(ull v, float &lo, float &hi){
    asm("mov.b64 {%0,%1}, %2;" : "=f"(lo), "=f"(hi) : "l"(v));
}
__device__ __forceinline__ ull ffma2(ull a, ull b, ull c){
    ull d; asm("fma.rn.f32x2 %0, %1, %2, %3;" : "=l"(d) : "l"(a), "l"(b), "l"(c)); return d;
}
__device__ __forceinline__ ull fmul2(ull a, ull b){
    ull d; asm("mul.rn.f32x2 %0, %1, %2;" : "=l"(d) : "l"(a), "l"(b)); return d;
}
__device__ __forceinline__ ull fadd2(ull a, ull b){
    ull d; asm("add.rn.f32x2 %0, %1, %2;" : "=l"(d) : "l"(a), "l"(b)); return d;
}
__device__ __forceinline__ float hsum2(ull v){ float lo, hi; unpack2(v, lo, hi); return lo + hi; }

// ---------------- scratch (static __device__, no allocs) ----------------
__device__ __align__(16) float  g_part[16*16*4160];
__device__ float4 g_pack[16*4096];      // {wx=sg, wy=sb+Ps_ln, wz=ng, ww=nb+Mprev_ln}
__device__ float  g_Pz[16*64];          // P_z_ln last step per batch
__device__ double g_std[1024];          // per-chunk-CTA {sum, sumsq}
__device__ volatile int g_fp[64];       // prompt-ready flags (per batch)
__device__ volatile int g_fc[1024];     // chunk-partials-ready flags (per chunk CTA)

__device__ __forceinline__ float eluf(float x){ return x > 0.f ? x : (expf(x) - 1.f); }

// one-sync block reduce for 256 threads (8 warps). red: >= 8*N floats.
template<int N>
__device__ __forceinline__ void block_reduce_b(const float* v, float* red, float* out){
    int lane = threadIdx.x & 31, w = threadIdx.x >> 5;
    #pragma unroll
    for (int i = 0; i < N; i++){
        float x = v[i];
        #pragma unroll
        for (int o = 16; o; o >>= 1) x += __shfl_xor_sync(0xffffffffu, x, o);
        if (lane == 0) red[w*N + i] = x;
    }
    __syncthreads();
    #pragma unroll
    for (int i = 0; i < N; i++){
        float s = 0.f;
        #pragma unroll
        for (int ww2 = 0; ww2 < 8; ww2++) s += red[ww2*N + i];
        out[i] = s;
    }
}

// smem layout constants for the chunk branch (floats)
#define SM_Z     0        // 2048
#define SM_V     2048     // 2048
#define SM_Q     4096     // 2048
#define SM_MOM   6144     // 3072 (32 steps * 8 warps * 3 float4)
#define SM_SCAL  9216     // 256  (32 * 2 float4)
#define SM_NAS   9472     // 8192 (aliases xsT during GEMV)
#define SM_XST   9472     // 2304 (64*36)
#define SM_CRED  17664    // 64
#define SM_DB    17728    // 8 (double[4])
#define SM_TOTAL 17736

// ================= fused kernel: prompt CTAs [0,B), chunk CTAs [B, B+B*NCH) ==
__global__ __launch_bounds__(256, 2)
void k_all(const int* uid, const float* X, const float* Pm, const float* Sm,
           const float* Wq, const float* bq, const float* Wk, const float* bk,
           const float* Wv, const float* bv,
           const float* zg, const float* zb, const float* sg, const float* sb,
           const float* ng, const float* nb,
           const float* nag, const float* nab,
           const float* pzbuf, const float* psbuf,
           float* out, int NCH, int LP, int B)
{
    extern __shared__ __align__(16) float SM[];
    int tid = threadIdx.x;
    int bi = blockIdx.x;
    int lane = tid & 31, w = tid >> 5;

    if (bi < B){
        // ================ prompt branch ================
        float* xsA  = SM;          float* xsB  = SM + 512;
        float* zbA  = SM + 1024;   float* zbB  = SM + 1536;
        float* vbA  = SM + 2048;   float* vbB  = SM + 2560;
        float* bufA = SM + 3072;   float* bufB = SM + 7168;
        float* zl   = SM + 11264;
        float* redA = SM + 11328;  float* redB = SM + 11344;

        int b = bi;
        int p = tid & 63, d0 = (tid >> 6) * 16;

        for (int i = tid; i < 512; i += 256){ xsA[i] = 0.f; xsB[i] = 0.f; }
        for (int i = tid; i < LP*64; i += 256){
            xsA[i] = Pm[b*LP*64 + i];
            xsB[i] = Sm[b*LP*64 + i];
        }
        __syncthreads();

        {
            int pass = tid >> 7, dt = (tid >> 6) & 1, col = tid & 63;
            const float* xp = pass ? xsB : xsA;
            float* zp = pass ? zbB : zbA;
            float* vp = pass ? vbB : vbA;
            const float* W  = dt ? Wv : Wk;
            float bb = dt ? bv[col] : bk[col];
            float acc8[8];
            #pragma unroll
            for (int l = 0; l < 8; l++) acc8[l] = bb;
            #pragma unroll 4
            for (int k = 0; k < 64; k++){
                float wv2 = W[k*64 + col];
                #pragma unroll
                for (int l = 0; l < 8; l++) acc8[l] += xp[l*64 + k] * wv2;
            }
            if (dt == 0){
                #pragma unroll
                for (int l = 0; l < 8; l++) zp[l*64 + col] = eluf(acc8[l]);
            } else {
                #pragma unroll
                for (int l = 0; l < 8; l++) vp[l*64 + col] = acc8[l];
            }
        }
        __syncthreads();

        float accP[16], accS[16];
        #pragma unroll
        for (int i = 0; i < 16; i++){ accP[i] = 0.f; accS[i] = 0.f; }
        for (int l = 0; l < LP; l++){
            float vvP = vbA[l*64 + p], vvS = vbB[l*64 + p];
            #pragma unroll
            for (int i = 0; i < 16; i++){
                accP[i] += zbA[l*64 + d0 + i] * vvP;
                accS[i] += zbB[l*64 + d0 + i] * vvS;
            }
        }
        float zsP = 0.f, zsS = 0.f;
        if (tid < 64){
            for (int l = 0; l < LP; l++){ zsP += zbA[l*64 + tid]; zsS += zbB[l*64 + tid]; }
        }

        float rv[2], out2[2];
        rv[0] = (tid < 64) ? zsP : 0.f; rv[1] = (tid < 64) ? zsP*zsP : 0.f;
        block_reduce_b<2>(rv, redA, out2);
        {
            float mz = out2[0]*(1.f/64.f);
            float ivz = rsqrtf(out2[1]*(1.f/64.f) - mz*mz + LN_EPS);
            if (tid < 64) g_Pz[b*64 + tid] = (zsP - mz)*ivz*zg[tid] + zb[tid];
        }
        rv[0] = (tid < 64) ? zsS : 0.f; rv[1] = (tid < 64) ? zsS*zsS : 0.f;
        block_reduce_b<2>(rv, redB, out2);
        {
            float mz = out2[0]*(1.f/64.f);
            float ivz = rsqrtf(out2[1]*(1.f/64.f) - mz*mz + LN_EPS);
            if (tid < 64) zl[tid] = (zsS - mz)*ivz*zg[tid] + zb[tid];
        }
        float sv[2];
        sv[0] = 0.f; sv[1] = 0.f;
        #pragma unroll
        for (int i = 0; i < 16; i++){ sv[0] += accP[i]; sv[1] += accP[i]*accP[i]; }
        block_reduce_b<2>(sv, redA, out2);
        {
            float ms = out2[0]*(1.f/4096.f);
            float ivs = rsqrtf(out2[1]*(1.f/4096.f) - ms*ms + LN_EPS);
            #pragma unroll
            for (int i = 0; i < 16; i++){
                int e = (d0 + i)*64 + p;
                bufA[e] = (accP[i] - ms)*ivs*sg[e] + sb[e];
            }
        }
        sv[0] = 0.f; sv[1] = 0.f;
        #pragma unroll
        for (int i = 0; i < 16; i++){ sv[0] += accS[i]; sv[1] += accS[i]*accS[i]; }
        block_reduce_b<2>(sv, redB, out2);
        {
            float ms = out2[0]*(1.f/4096.f);
            float ivs = rsqrtf(out2[1]*(1.f/4096.f) - ms*ms + LN_EPS);
            #pragma unroll
            for (int i = 0; i < 16; i++){
                int e = (d0 + i)*64 + p;
                bufB[e] = (accS[i] - ms)*ivs*sg[e] + sb[e];
            }
        }
        __syncthreads();

        int u = uid[b];
        float pzv = 0.f;
        if (tid < 64) pzv = pzbuf[(size_t)u*64 + tid] + zl[tid];
        float rv1[1], out1[1];
        rv1[0] = (tid < 64) ? pzv*pzv : 0.f;
        block_reduce_b<1>(rv1, redA, out1);
        float ipn = 1.f / (fmaxf(sqrtf(out1[0]), 1e-8f) + EPS);

        float pn16[16];
        sv[0] = 0.f; sv[1] = 0.f;
        #pragma unroll
        for (int k2 = 0; k2 < 16; k2++){
            int e = tid + k2*256;
            float pv = (psbuf[(size_t)u*4096 + e] + bufB[e]) * ipn;
            pn16[k2] = pv; sv[0] += pv; sv[1] += pv*pv;
        }
        block_reduce_b<2>(sv, redB, out2);
        float mp = out2[0]*(1.f/4096.f);
        float ivp = rsqrtf(out2[1]*(1.f/4096.f) - mp*mp + LN_EPS);
        #pragma unroll
        for (int k2 = 0; k2 < 16; k2++){
            int e = tid + k2*256;
            float M = (pn16[k2] - mp)*ivp*ng[e] + nb[e];
            g_pack[b*4096 + e] = make_float4(sg[e], sb[e] + bufA[e], ng[e], nb[e] + M);
        }
        // publish prompt results
        __threadfence();
        __syncthreads();
        if (tid == 0) g_fp[b] = 1;
        return;
    }

    // ================ chunk branch ================
    float*  ztile = SM + SM_Z;
    float*  vtile = SM + SM_V;
    float*  qtile = SM + SM_Q;
    float4* mom4  = (float4*)(SM + SM_MOM);
    float4* scal4 = (float4*)(SM + SM_SCAL);
    float*  na_s  = SM + SM_NAS;
    float*  xsT   = SM + SM_XST;       // aliases na_s (GEMV phase only)
    float*  cred  = SM + SM_CRED;
    double* db    = (double*)(SM + SM_DB);

    int pid = bi - B;
    int b = pid / NCH, ch = pid % NCH;
    int p = tid & 63, d0 = (tid >> 6) * 16;
    int L = NCH * CHUNK;
    size_t xbase = ((size_t)b*L + (size_t)ch*CHUNK) * 64;

    // ---- GEMV phase: load+transpose X, compute q/z/v straight into smem ----
    #pragma unroll
    for (int i = 0; i < 8; i++){
        int e = tid + i*256;
        int l = e >> 6, k = e & 63;
        xsT[k*36 + l] = X[xbase + e];
    }
    __syncthreads();

    if (tid < 192){
        int dt = tid >> 6, col = tid & 63;
        const float* W = (dt == 0) ? Wq : ((dt == 1) ? Wk : Wv);
        float bb = (dt == 0) ? bq[col] : ((dt == 1) ? bk[col] : bv[col]);
        ull bb2 = pack2(bb, bb);
        ull acc2[16];
        #pragma unroll
        for (int j = 0; j < 16; j++) acc2[j] = bb2;
        #pragma unroll 4
        for (int k = 0; k < 64; k++){
            float wv2 = W[k*64 + col];
            ull wp = pack2(wv2, wv2);
            const ulonglong2* xr = (const ulonglong2*)&xsT[k*36];
            #pragma unroll
            for (int j4 = 0; j4 < 8; j4++){
                ulonglong2 xx = xr[j4];
                acc2[j4*2+0] = ffma2(xx.x, wp, acc2[j4*2+0]);
                acc2[j4*2+1] = ffma2(xx.y, wp, acc2[j4*2+1]);
            }
        }
        float* dst = (dt == 0) ? qtile : ((dt == 1) ? ztile : vtile);
        if (dt == 2){
            #pragma unroll
            for (int j = 0; j < 16; j++){
                float a, b2; unpack2(acc2[j], a, b2);
                dst[(2*j  )*64 + col] = a;
                dst[(2*j+1)*64 + col] = b2;
            }
        } else {
            #pragma unroll
            for (int j = 0; j < 16; j++){
                float a, b2; unpack2(acc2[j], a, b2);
                dst[(2*j  )*64 + col] = eluf(a);
                dst[(2*j+1)*64 + col] = eluf(b2);
            }
        }
    }
    __syncthreads();

    // ---- own-chunk partial sums -> g_part, publish flag ----
    {
        ull acc2o[8];
        #pragma unroll
        for (int j = 0; j < 8; j++) acc2o[j] = 0ull;
        #pragma unroll 4
        for (int l = 0; l < 32; l++){
            float vv = vtile[l*64 + p];
            ull vvp = pack2(vv, vv);
            const ulonglong2* zb2p = (const ulonglong2*)&ztile[l*64 + d0];
            #pragma unroll
            for (int j4 = 0; j4 < 4; j4++){
                ulonglong2 zz = zb2p[j4];
                acc2o[j4*2+0] = ffma2(zz.x, vvp, acc2o[j4*2+0]);
                acc2o[j4*2+1] = ffma2(zz.y, vvp, acc2o[j4*2+1]);
            }
        }
        size_t o = (size_t)pid * 4160;
        #pragma unroll
        for (int j = 0; j < 8; j++){
            float a, b2; unpack2(acc2o[j], a, b2);
            g_part[o + (d0 + 2*j  )*64 + p] = a;
            g_part[o + (d0 + 2*j+1)*64 + p] = b2;
        }
        if (tid < 64){
            float zs = 0.f;
            #pragma unroll 4
            for (int l = 0; l < 32; l++) zs += ztile[l*64 + tid];
            g_part[o + 4096 + tid] = zs;
        }
        __threadfence();
        __syncthreads();
        if (tid == 0) g_fc[pid] = 1;
    }

    // ---- wait for prompt results, then prefix partials ----
    if (tid == 0){
        while (g_fp[b] == 0) __nanosleep(64);
        for (int c2 = 0; c2 < ch; c2++)
            while (g_fc[b*NCH + c2] == 0) __nanosleep(64);
    }
    __syncthreads();
    __threadfence();

    // packed constants -> registers
    ull wx2[8], wy2[8], wz2[8], ww2[8];
    {
        const float4* pk = &g_pack[b*4096];
        #pragma unroll
        for (int j = 0; j < 8; j++){
            float4 ta = pk[(d0 + 2*j    )*64 + p];
            float4 tb = pk[(d0 + 2*j + 1)*64 + p];
            wx2[j] = pack2(ta.x, tb.x);
            wy2[j] = pack2(ta.y, tb.y);
            wz2[j] = pack2(ta.z, tb.z);
            ww2[j] = pack2(ta.w, tb.w);
        }
    }
    float zpxv = 0.f, zpyv = 0.f;
    if (tid < 64){ zpxv = zg[tid]; zpyv = zb[tid] + g_Pz[b*64 + tid]; }
    float ngA = nag[lane], ngB = nag[lane+32];
    float nbA = nab[lane], nbB = nab[lane+32];

    // exclusive prefix over prior chunks' partials -> packed A2
    ull A2[8];
    float zc = 0.f;
    {
        float A[16];
        #pragma unroll
        for (int i = 0; i < 16; i++) A[i] = 0.f;
        for (int c2 = 0; c2 < ch; c2++){
            const float* gp = &g_part[(size_t)(b*NCH + c2) * 4160];
            #pragma unroll
            for (int i = 0; i < 16; i++) A[i] += gp[(d0 + i)*64 + p];
            if (tid < 64) zc += gp[4096 + tid];
        }
        #pragma unroll
        for (int j = 0; j < 8; j++) A2[j] = pack2(A[2*j], A[2*j+1]);
    }

    // per-CTA constants (one block reduce)
    float Cwx, Cwx2, Cwxwy, Cwy, Cwy2, Czpx2, Czpxzpy, Czpy2;
    {
        ull c0p = 0ull, c1p = 0ull, c2p = 0ull, c3p = 0ull, c4p = 0ull;
        #pragma unroll
        for (int j = 0; j < 8; j++){
            c0p = fadd2(c0p, wx2[j]);
            c1p = ffma2(wx2[j], wx2[j], c1p);
            c2p = ffma2(wx2[j], wy2[j], c2p);
            c3p = fadd2(c3p, wy2[j]);
            c4p = ffma2(wy2[j], wy2[j], c4p);
        }
        float cv[8];
        cv[0] = hsum2(c0p); cv[1] = hsum2(c1p); cv[2] = hsum2(c2p);
        cv[3] = hsum2(c3p); cv[4] = hsum2(c4p);
        cv[5] = zpxv*zpxv; cv[6] = zpxv*zpyv; cv[7] = zpyv*zpyv;  // 0 for tid>=64
        #pragma unroll
        for (int k = 0; k < 8; k++){
            #pragma unroll
            for (int o = 16; o; o >>= 1) cv[k] += __shfl_xor_sync(0xffffffffu, cv[k], o);
        }
        if (lane == 0){
            #pragma unroll
            for (int k = 0; k < 8; k++) cred[w*8 + k] = cv[k];
        }
        __syncthreads();
        float s[8];
        #pragma unroll
        for (int k = 0; k < 8; k++){
            float t = 0.f;
            #pragma unroll
            for (int w2 = 0; w2 < 8; w2++) t += cred[w2*8 + k];
            s[k] = t;
        }
        Cwx=s[0]; Cwx2=s[1]; Cwxwy=s[2]; Cwy=s[3]; Cwy2=s[4];
        Czpx2=s[5]; Czpxzpy=s[6]; Czpy2=s[7];
    }
    const float inv4096 = 1.f/4096.f, inv64 = 1.f/64.f;

    // ================= PASS 1: moments (packed), no syncs =================
    #pragma unroll 1
    for (int r = 0; r < CHUNK; r++){
        const ulonglong2* z2p = (const ulonglong2*)&ztile[r*64 + d0];
        float vv = vtile[r*64 + p];
        ull vv2 = pack2(vv, vv);
        ull pS = 0ull, pS2 = 0ull, pU = 0ull, pU2 = 0ull, pUwx = 0ull, pUwy = 0ull;
        #pragma unroll
        for (int j4 = 0; j4 < 4; j4++){
            ulonglong2 zz = z2p[j4];
            #pragma unroll
            for (int c = 0; c < 2; c++){
                int j = j4*2 + c;
                ull zp = c ? zz.y : zz.x;
                A2[j] = ffma2(zp, vv2, A2[j]);
                pS  = fadd2(pS, A2[j]);
                pS2 = ffma2(A2[j], A2[j], pS2);
                ull uu = fmul2(A2[j], wx2[j]);
                pU   = fadd2(pU, uu);
                pU2  = ffma2(uu, uu, pU2);
                pUwx = ffma2(uu, wx2[j], pUwx);
                pUwy = ffma2(uu, wy2[j], pUwy);
            }
        }
        float sA = hsum2(pS),  sA2 = hsum2(pS2), sU = hsum2(pU);
        float sU2 = hsum2(pU2), sUwx = hsum2(pUwx), sUwy = hsum2(pUwy);

        float r6 = 0.f, r7 = 0.f, r8 = 0.f, r9 = 0.f, r10 = 0.f, r11 = 0.f;
        if (tid < 64){
            zc += ztile[r*64 + tid];
            float qv = qtile[r*64 + tid];
            float y = zc * zpxv;
            r6 = zc; r7 = zc*zc; r8 = y*y; r9 = y*zpyv; r10 = y*zpxv; r11 = qv*qv;
        }
        #pragma unroll
        for (int o = 16; o; o >>= 1){
            sA   += __shfl_xor_sync(0xffffffffu, sA, o);
            sA2  += __shfl_xor_sync(0xffffffffu, sA2, o);
            sU   += __shfl_xor_sync(0xffffffffu, sU, o);
            sU2  += __shfl_xor_sync(0xffffffffu, sU2, o);
            sUwx += __shfl_xor_sync(0xffffffffu, sUwx, o);
            sUwy += __shfl_xor_sync(0xffffffffu, sUwy, o);
        }
        if (w < 2){
            #pragma unroll
            for (int o = 16; o; o >>= 1){
                r6  += __shfl_xor_sync(0xffffffffu, r6, o);
                r7  += __shfl_xor_sync(0xffffffffu, r7, o);
                r8  += __shfl_xor_sync(0xffffffffu, r8, o);
                r9  += __shfl_xor_sync(0xffffffffu, r9, o);
                r10 += __shfl_xor_sync(0xffffffffu, r10, o);
                r11 += __shfl_xor_sync(0xffffffffu, r11, o);
            }
        }
        if (lane == 0){
            int mbase = (r*8 + w)*3;
            mom4[mbase + 0] = make_float4(sA, sA2, sU, sU2);
            mom4[mbase + 1] = make_float4(sUwx, sUwy, r6, r7);
            mom4[mbase + 2] = make_float4(r8, r9, r10, r11);
        }
    }
    __syncthreads();

    // ================= SCALAR PHASE: thread tid<32 owns step tid ==========
    if (tid < 32){
        int r = tid;
        float4 a0 = make_float4(0,0,0,0), a1 = a0, a2v = a0;
        #pragma unroll
        for (int w2 = 0; w2 < 8; w2++){
            int mbase = (r*8 + w2)*3;
            float4 t0 = mom4[mbase], t1 = mom4[mbase+1], t2 = mom4[mbase+2];
            a0.x += t0.x; a0.y += t0.y; a0.z += t0.z; a0.w += t0.w;
            a1.x += t1.x; a1.y += t1.y; a1.z += t1.z; a1.w += t1.w;
            a2v.x += t2.x; a2v.y += t2.y; a2v.z += t2.z; a2v.w += t2.w;
        }
        float aBar = a0.x * inv4096;
        float ivs  = rsqrtf(a0.y*inv4096 - aBar*aBar + LN_EPS);
        float c0   = aBar * ivs;
        float Sst  = ivs*a0.z - c0*Cwx + Cwy;
        float Sst2 = ivs*ivs*a0.w + 2.f*ivs*(a1.y - c0*a1.x)
                   + Cwy2 - 2.f*c0*Cwxwy + c0*c0*Cwx2;
        float mzv  = a1.z * inv64;
        float ivz  = rsqrtf(a1.w*inv64 - mzv*mzv + LN_EPS);
        float dd0  = mzv * ivz;
        float Szt2 = ivz*ivz*a2v.x + 2.f*ivz*(a2v.y - dd0*a2v.z)
                   + Czpy2 - 2.f*dd0*Czpxzpy + dd0*dd0*Czpx2;
        float zn   = fmaxf(sqrtf(Szt2), 1e-8f);
        float izn  = 1.f / zn;
        float mst  = Sst * inv4096;
        float mnam = mst * izn;
        float vnam = (Sst2*inv4096 - mst*mst) * izn * izn;
        float ivn  = rsqrtf(vnam + LN_EPS);
        float k1   = izn * ivn, k0 = -mnam * ivn;
        float srq  = 1.f / fmaxf(sqrtf(a2v.w), 1e-8f);
        float f1 = k1 * ivs, f2 = -f1 * aBar, f3 = k1;
        scal4[r*2 + 0] = make_float4(f1, f2, f3, k0);
        scal4[r*2 + 1] = make_float4(srq, mzv, ivz, 0.f);
    }
    __syncthreads();

    // ================= PASS 2: backward (packed), no syncs =================
    float fsum = 0.f, fsq = 0.f;
    #pragma unroll 1
    for (int r = CHUNK - 1; r >= 0; r--){
        float4 s0 = scal4[r*2 + 0];
        ull f1p = pack2(s0.x, s0.x), f2p = pack2(s0.y, s0.y);
        ull f3p = pack2(s0.z, s0.z), k0p = pack2(s0.w, s0.w);
        const ulonglong2* z2p = (const ulonglong2*)&ztile[r*64 + d0];
        const ulonglong2* q2p = (const ulonglong2*)&qtile[r*64 + d0];
        float vv = vtile[r*64 + p];
        ull nvv2 = pack2(-vv, -vv);
        ull pacc = 0ull;
        #pragma unroll
        for (int j4 = 0; j4 < 4; j4++){
            ulonglong2 zz = z2p[j4];
            ulonglong2 qq = q2p[j4];
            #pragma unroll
            for (int c = 0; c < 2; c++){
                int j = j4*2 + c;
                ull zp = c ? zz.y : zz.x;
                ull qp = c ? qq.y : qq.x;
                ull uu = fmul2(A2[j], wx2[j]);
                ull aa = ffma2(f1p, uu, k0p);
                aa = ffma2(f2p, wx2[j], aa);
                aa = ffma2(f3p, wy2[j], aa);
                ull t = ffma2(aa, wz2[j], ww2[j]);
                pacc = ffma2(qp, t, pacc);
                A2[j] = ffma2(zp, nvv2, A2[j]);    // step back to A_{r-1}
            }
        }
        na_s[r*256 + tid] = hsum2(pacc);
        if (tid < 64){
            float4 s1 = scal4[r*2 + 1];
            float zt = (zc - s1.y)*s1.z*zpxv + zpyv;
            float rr = qtile[r*64 + tid] / fmaxf(zt, 1e-6f);
            fsum += rr; fsq = fmaf(rr, rr, fsq);
            zc -= ztile[r*64 + tid];
        }
    }
    // per-CTA std partials (deterministic, no atomics)
    if (tid < 64){
        float s1 = fsum, s2 = fsq;
        #pragma unroll
        for (int o = 16; o; o >>= 1){
            s1 += __shfl_xor_sync(0xffffffffu, s1, o);
            s2 += __shfl_xor_sync(0xffffffffu, s2, o);
        }
        if (lane == 0){ db[(tid>>5)*2] = (double)s1; db[(tid>>5)*2 + 1] = (double)s2; }
    }
    __syncthreads();
    if (tid == 0){
        g_std[pid*2 + 0] = db[0] + db[2];
        g_std[pid*2 + 1] = db[1] + db[3];
    }

    // ================= EPILOGUE: warp w -> steps w*4 .. w*4+3 ==============
    #pragma unroll
    for (int rr = 0; rr < 4; rr++){
        int r = w*4 + rr;
        float srq = scal4[r*2 + 1].x;
        const float* np = &na_s[r*256];
        float nvA = (np[lane] + np[lane+64] + np[lane+128] + np[lane+192]) * srq;
        float nvB = (np[lane+32] + np[lane+96] + np[lane+160] + np[lane+224]) * srq;
        float s1 = nvA + nvB, s2 = nvA*nvA + nvB*nvB;
        #pragma unroll
        for (int o = 16; o; o >>= 1){
            s1 += __shfl_xor_sync(0xffffffffu, s1, o);
            s2 += __shfl_xor_sync(0xffffffffu, s2, o);
        }
        float mn = s1 * inv64;
        float iv = rsqrtf(s2*inv64 - mn*mn + LN_EPS);
        float* op = out + xbase + (size_t)r*64;
        op[lane]      = (nvA - mn)*iv*ngA + nbA;
        op[lane + 32] = (nvB - mn)*iv*ngB + nbB;
    }
}

// ---------------- kernel E: finalize std (deterministic tree) ----------------
__global__ void k_std(float* out, int n, int outpos, int nph)
{
    __shared__ double sm[512];
    int t = threadIdx.x;
    double a = 0.0, c = 0.0;
    for (int i = t; i < nph; i += 256){ a += g_std[i*2]; c += g_std[i*2 + 1]; }
    sm[t] = a; sm[256 + t] = c;
    __syncthreads();
    for (int s = 128; s; s >>= 1){
        if (t < s){ sm[t] += sm[t + s]; sm[256 + t] += sm[256 + t + s]; }
        __syncthreads();
    }
    if (t == 0){
        double mean = sm[0] / (double)n;
        double var  = (sm[256] - sm[0]*mean) / (double)(n - 1);
        out[outpos] = (float)sqrt(var);
    }
}

// ---------------- launch ----------------
extern "C" void kernel_launch(void* const* d_in, const int* in_sizes, int n_in,
                              void* d_out, int out_size)
{
    const int*   uid   = (const int*)  d_in[0];
    const float* X     = (const float*)d_in[1];
    const float* Pm    = (const float*)d_in[2];
    const float* Sm    = (const float*)d_in[3];
    const float* Wq    = (const float*)d_in[4];
    const float* bq    = (const float*)d_in[5];
    const float* Wk    = (const float*)d_in[6];
    const float* bk    = (const float*)d_in[7];
    const float* Wv    = (const float*)d_in[8];
    const float* bv    = (const float*)d_in[9];
    const float* zg    = (const float*)d_in[10];
    const float* zb    = (const float*)d_in[11];
    const float* sg    = (const float*)d_in[12];
    const float* sb    = (const float*)d_in[13];
    const float* ng    = (const float*)d_in[14];
    const float* nb    = (const float*)d_in[15];
    const float* nag   = (const float*)d_in[16];
    const float* nab   = (const float*)d_in[17];
    const float* pzbuf = (const float*)d_in[18];
    const float* psbuf = (const float*)d_in[19];
    float* out = (float*)d_out;

    int B   = in_sizes[0];
    int L   = in_sizes[1] / (B * 64);
    int NCH = L / CHUNK;
    int LP  = in_sizes[2] / (B * 64);
    int NPH = B * NCH;

    size_t smAll = (size_t)SM_TOTAL * 4;   // ~71 KB dynamic
    cudaFuncSetAttribute(k_all, cudaFuncAttributeMaxDynamicSharedMemorySize, (int)smAll);

    k_all<<<B + NPH, 256, smAll>>>(uid, X, Pm, Sm, Wq, bq, Wk, bk, Wv, bv,
                                   zg, zb, sg, sb, ng, nb, nag, nab,
                                   pzbuf, psbuf, out, NCH, LP, B);
    k_std<<<1, 256>>>(out, B*L*64, out_size - 1, NPH);
}

// round 15
// speedup vs baseline: 1.4803x; 1.0336x over previous
#include <cuda_runtime.h>
#include <math.h>

#define EPS 1e-8f
#define LN_EPS 1e-5f
#define CHUNK 32

typedef unsigned long long ull;

// ---------------- packed f32x2 helpers (sm_103a) ----------------
__device__ __forceinline__ ull pack2(float lo, float hi){
    ull r; asm("mov.b64 %0, {%1,%2};" : "=l"(r) : "f"(lo), "f"(hi)); return r;
}
__device__ __forceinline__ void unpack2(ull v, float &lo, float &hi){
    asm("mov.b64 {%0,%1}, %2;" : "=f"(lo), "=f"(hi) : "l"(v));
}
__device__ __forceinline__ ull ffma2(ull a, ull b, ull c){
    ull d; asm("fma.rn.f32x2 %0, %1, %2, %3;" : "=l"(d) : "l"(a), "l"(b), "l"(c)); return d;
}
__device__ __forceinline__ ull fmul2(ull a, ull b){
    ull d; asm("mul.rn.f32x2 %0, %1, %2;" : "=l"(d) : "l"(a), "l"(b)); return d;
}
__device__ __forceinline__ ull fadd2(ull a, ull b){
    ull d; asm("add.rn.f32x2 %0, %1, %2;" : "=l"(d) : "l"(a), "l"(b)); return d;
}
__device__ __forceinline__ float hsum2(ull v){ float lo, hi; unpack2(v, lo, hi); return lo + hi; }

// ---------------- scratch (static __device__, no allocs) ----------------
__device__ __align__(16) float  g_part[16*16*4160];
__device__ float4 g_pack[16*4096];      // {wx=sg, wy=sb+Ps_ln, wz=ng, ww=nb+Mprev_ln}
__device__ float  g_Pz[16*64];          // P_z_ln last step per batch
__device__ double g_std[1024];          // per-chunk-CTA {sum, sumsq}
__device__ volatile int g_fp[64];       // prompt-ready flags (per batch)
__device__ volatile int g_fc[1024];     // chunk-partials-ready flags (per chunk CTA)
__device__ unsigned int g_cnt;          // monotonic completion counter (never reset)

__device__ __forceinline__ float eluf(float x){ return x > 0.f ? x : (expf(x) - 1.f); }

// one-sync block reduce for 256 threads (8 warps). red: >= 8*N floats.
template<int N>
__device__ __forceinline__ void block_reduce_b(const float* v, float* red, float* out){
    int lane = threadIdx.x & 31, w = threadIdx.x >> 5;
    #pragma unroll
    for (int i = 0; i < N; i++){
        float x = v[i];
        #pragma unroll
        for (int o = 16; o; o >>= 1) x += __shfl_xor_sync(0xffffffffu, x, o);
        if (lane == 0) red[w*N + i] = x;
    }
    __syncthreads();
    #pragma unroll
    for (int i = 0; i < N; i++){
        float s = 0.f;
        #pragma unroll
        for (int ww2 = 0; ww2 < 8; ww2++) s += red[ww2*N + i];
        out[i] = s;
    }
}

// smem layout constants for the chunk branch (floats)
#define SM_Z     0        // 2048
#define SM_V     2048     // 2048
#define SM_Q     4096     // 2048
#define SM_MOM   6144     // 3072 (32 steps * 8 warps * 3 float4)
#define SM_SCAL  9216     // 256  (32 * 2 float4)
#define SM_NAS   9472     // 8192 (aliases xsT during GEMV)
#define SM_XST   9472     // 2304 (64*36)
#define SM_CRED  17664    // 64
#define SM_DB    17728    // 8 (double[4])
#define SM_TOTAL 17736

// ================= fused kernel: prompt CTAs [0,B), chunk CTAs [B, B+B*NCH) ==
__global__ __launch_bounds__(256, 2)
void k_all(const int* uid, const float* X, const float* Pm, const float* Sm,
           const float* Wq, const float* bq, const float* Wk, const float* bk,
           const float* Wv, const float* bv,
           const float* zg, const float* zb, const float* sg, const float* sb,
           const float* ng, const float* nb,
           const float* nag, const float* nab,
           const float* pzbuf, const float* psbuf,
           float* out, int NCH, int LP, int B, int nStd, int outpos)
{
    extern __shared__ __align__(16) float SM[];
    __shared__ int sIsLast;
    __shared__ double sred[64];
    int tid = threadIdx.x;
    int bi = blockIdx.x;
    int lane = tid & 31, w = tid >> 5;

    if (bi < B){
        // ================ prompt branch ================
        float* xsA  = SM;          float* xsB  = SM + 512;
        float* zbA  = SM + 1024;   float* zbB  = SM + 1536;
        float* vbA  = SM + 2048;   float* vbB  = SM + 2560;
        float* bufA = SM + 3072;   float* bufB = SM + 7168;
        float* zl   = SM + 11264;
        float* redA = SM + 11328;  float* redB = SM + 11344;

        int b = bi;
        int p = tid & 63, d0 = (tid >> 6) * 16;

        for (int i = tid; i < 512; i += 256){ xsA[i] = 0.f; xsB[i] = 0.f; }
        for (int i = tid; i < LP*64; i += 256){
            xsA[i] = Pm[b*LP*64 + i];
            xsB[i] = Sm[b*LP*64 + i];
        }
        __syncthreads();

        {
            int pass = tid >> 7, dt = (tid >> 6) & 1, col = tid & 63;
            const float* xp = pass ? xsB : xsA;
            float* zp = pass ? zbB : zbA;
            float* vp = pass ? vbB : vbA;
            const float* W  = dt ? Wv : Wk;
            float bb = dt ? bv[col] : bk[col];
            float acc8[8];
            #pragma unroll
            for (int l = 0; l < 8; l++) acc8[l] = bb;
            #pragma unroll 4
            for (int k = 0; k < 64; k++){
                float wv2 = W[k*64 + col];
                #pragma unroll
                for (int l = 0; l < 8; l++) acc8[l] += xp[l*64 + k] * wv2;
            }
            if (dt == 0){
                #pragma unroll
                for (int l = 0; l < 8; l++) zp[l*64 + col] = eluf(acc8[l]);
            } else {
                #pragma unroll
                for (int l = 0; l < 8; l++) vp[l*64 + col] = acc8[l];
            }
        }
        __syncthreads();

        float accP[16], accS[16];
        #pragma unroll
        for (int i = 0; i < 16; i++){ accP[i] = 0.f; accS[i] = 0.f; }
        for (int l = 0; l < LP; l++){
            float vvP = vbA[l*64 + p], vvS = vbB[l*64 + p];
            #pragma unroll
            for (int i = 0; i < 16; i++){
                accP[i] += zbA[l*64 + d0 + i] * vvP;
                accS[i] += zbB[l*64 + d0 + i] * vvS;
            }
        }
        float zsP = 0.f, zsS = 0.f;
        if (tid < 64){
            for (int l = 0; l < LP; l++){ zsP += zbA[l*64 + tid]; zsS += zbB[l*64 + tid]; }
        }

        float rv[2], out2[2];
        rv[0] = (tid < 64) ? zsP : 0.f; rv[1] = (tid < 64) ? zsP*zsP : 0.f;
        block_reduce_b<2>(rv, redA, out2);
        {
            float mz = out2[0]*(1.f/64.f);
            float ivz = rsqrtf(out2[1]*(1.f/64.f) - mz*mz + LN_EPS);
            if (tid < 64) g_Pz[b*64 + tid] = (zsP - mz)*ivz*zg[tid] + zb[tid];
        }
        rv[0] = (tid < 64) ? zsS : 0.f; rv[1] = (tid < 64) ? zsS*zsS : 0.f;
        block_reduce_b<2>(rv, redB, out2);
        {
            float mz = out2[0]*(1.f/64.f);
            float ivz = rsqrtf(out2[1]*(1.f/64.f) - mz*mz + LN_EPS);
            if (tid < 64) zl[tid] = (zsS - mz)*ivz*zg[tid] + zb[tid];
        }
        float sv[2];
        sv[0] = 0.f; sv[1] = 0.f;
        #pragma unroll
        for (int i = 0; i < 16; i++){ sv[0] += accP[i]; sv[1] += accP[i]*accP[i]; }
        block_reduce_b<2>(sv, redA, out2);
        {
            float ms = out2[0]*(1.f/4096.f);
            float ivs = rsqrtf(out2[1]*(1.f/4096.f) - ms*ms + LN_EPS);
            #pragma unroll
            for (int i = 0; i < 16; i++){
                int e = (d0 + i)*64 + p;
                bufA[e] = (accP[i] - ms)*ivs*sg[e] + sb[e];
            }
        }
        sv[0] = 0.f; sv[1] = 0.f;
        #pragma unroll
        for (int i = 0; i < 16; i++){ sv[0] += accS[i]; sv[1] += accS[i]*accS[i]; }
        block_reduce_b<2>(sv, redB, out2);
        {
            float ms = out2[0]*(1.f/4096.f);
            float ivs = rsqrtf(out2[1]*(1.f/4096.f) - ms*ms + LN_EPS);
            #pragma unroll
            for (int i = 0; i < 16; i++){
                int e = (d0 + i)*64 + p;
                bufB[e] = (accS[i] - ms)*ivs*sg[e] + sb[e];
            }
        }
        __syncthreads();

        int u = uid[b];
        float pzv = 0.f;
        if (tid < 64) pzv = pzbuf[(size_t)u*64 + tid] + zl[tid];
        float rv1[1], out1[1];
        rv1[0] = (tid < 64) ? pzv*pzv : 0.f;
        block_reduce_b<1>(rv1, redA, out1);
        float ipn = 1.f / (fmaxf(sqrtf(out1[0]), 1e-8f) + EPS);

        float pn16[16];
        sv[0] = 0.f; sv[1] = 0.f;
        #pragma unroll
        for (int k2 = 0; k2 < 16; k2++){
            int e = tid + k2*256;
            float pv = (psbuf[(size_t)u*4096 + e] + bufB[e]) * ipn;
            pn16[k2] = pv; sv[0] += pv; sv[1] += pv*pv;
        }
        block_reduce_b<2>(sv, redB, out2);
        float mp = out2[0]*(1.f/4096.f);
        float ivp = rsqrtf(out2[1]*(1.f/4096.f) - mp*mp + LN_EPS);
        #pragma unroll
        for (int k2 = 0; k2 < 16; k2++){
            int e = tid + k2*256;
            float M = (pn16[k2] - mp)*ivp*ng[e] + nb[e];
            g_pack[b*4096 + e] = make_float4(sg[e], sb[e] + bufA[e], ng[e], nb[e] + M);
        }
        // publish prompt results
        __threadfence();
        __syncthreads();
        if (tid == 0) g_fp[b] = 1;
        return;
    }

    // ================ chunk branch ================
    float*  ztile = SM + SM_Z;
    float*  vtile = SM + SM_V;
    float*  qtile = SM + SM_Q;
    float4* mom4  = (float4*)(SM + SM_MOM);
    float4* scal4 = (float4*)(SM + SM_SCAL);
    float*  na_s  = SM + SM_NAS;
    float*  xsT   = SM + SM_XST;       // aliases na_s (GEMV phase only)
    float*  cred  = SM + SM_CRED;
    double* db    = (double*)(SM + SM_DB);

    int pid = bi - B;
    int b = pid / NCH, ch = pid % NCH;
    int p = tid & 63, d0 = (tid >> 6) * 16;
    int L = NCH * CHUNK;
    size_t xbase = ((size_t)b*L + (size_t)ch*CHUNK) * 64;

    // ---- GEMV phase: load+transpose X, compute q/z/v straight into smem ----
    #pragma unroll
    for (int i = 0; i < 8; i++){
        int e = tid + i*256;
        int l = e >> 6, k = e & 63;
        xsT[k*36 + l] = X[xbase + e];
    }
    __syncthreads();

    if (tid < 192){
        int dt = tid >> 6, col = tid & 63;
        const float* W = (dt == 0) ? Wq : ((dt == 1) ? Wk : Wv);
        float bb = (dt == 0) ? bq[col] : ((dt == 1) ? bk[col] : bv[col]);
        ull bb2 = pack2(bb, bb);
        ull acc2[16];
        #pragma unroll
        for (int j = 0; j < 16; j++) acc2[j] = bb2;
        #pragma unroll 4
        for (int k = 0; k < 64; k++){
            float wv2 = W[k*64 + col];
            ull wp = pack2(wv2, wv2);
            const ulonglong2* xr = (const ulonglong2*)&xsT[k*36];
            #pragma unroll
            for (int j4 = 0; j4 < 8; j4++){
                ulonglong2 xx = xr[j4];
                acc2[j4*2+0] = ffma2(xx.x, wp, acc2[j4*2+0]);
                acc2[j4*2+1] = ffma2(xx.y, wp, acc2[j4*2+1]);
            }
        }
        float* dst = (dt == 0) ? qtile : ((dt == 1) ? ztile : vtile);
        if (dt == 2){
            #pragma unroll
            for (int j = 0; j < 16; j++){
                float a, b2; unpack2(acc2[j], a, b2);
                dst[(2*j  )*64 + col] = a;
                dst[(2*j+1)*64 + col] = b2;
            }
        } else {
            #pragma unroll
            for (int j = 0; j < 16; j++){
                float a, b2; unpack2(acc2[j], a, b2);
                dst[(2*j  )*64 + col] = eluf(a);
                dst[(2*j+1)*64 + col] = eluf(b2);
            }
        }
    }
    __syncthreads();

    // ---- own-chunk partial sums -> g_part, publish flag ----
    {
        ull acc2o[8];
        #pragma unroll
        for (int j = 0; j < 8; j++) acc2o[j] = 0ull;
        #pragma unroll 4
        for (int l = 0; l < 32; l++){
            float vv = vtile[l*64 + p];
            ull vvp = pack2(vv, vv);
            const ulonglong2* zb2p = (const ulonglong2*)&ztile[l*64 + d0];
            #pragma unroll
            for (int j4 = 0; j4 < 4; j4++){
                ulonglong2 zz = zb2p[j4];
                acc2o[j4*2+0] = ffma2(zz.x, vvp, acc2o[j4*2+0]);
                acc2o[j4*2+1] = ffma2(zz.y, vvp, acc2o[j4*2+1]);
            }
        }
        size_t o = (size_t)pid * 4160;
        #pragma unroll
        for (int j = 0; j < 8; j++){
            float a, b2; unpack2(acc2o[j], a, b2);
            g_part[o + (d0 + 2*j  )*64 + p] = a;
            g_part[o + (d0 + 2*j+1)*64 + p] = b2;
        }
        if (tid < 64){
            float zs = 0.f;
            #pragma unroll 4
            for (int l = 0; l < 32; l++) zs += ztile[l*64 + tid];
            g_part[o + 4096 + tid] = zs;
        }
        __threadfence();
        __syncthreads();
        if (tid == 0) g_fc[pid] = 1;
    }

    // ---- wait for prompt results, then prefix partials ----
    if (tid == 0){
        while (g_fp[b] == 0) __nanosleep(64);
        for (int c2 = 0; c2 < ch; c2++)
            while (g_fc[b*NCH + c2] == 0) __nanosleep(64);
    }
    __syncthreads();
    __threadfence();

    // packed constants -> registers
    ull wx2[8], wy2[8], wz2[8], ww2[8];
    {
        const float4* pk = &g_pack[b*4096];
        #pragma unroll
        for (int j = 0; j < 8; j++){
            float4 ta = pk[(d0 + 2*j    )*64 + p];
            float4 tb = pk[(d0 + 2*j + 1)*64 + p];
            wx2[j] = pack2(ta.x, tb.x);
            wy2[j] = pack2(ta.y, tb.y);
            wz2[j] = pack2(ta.z, tb.z);
            ww2[j] = pack2(ta.w, tb.w);
        }
    }
    float zpxv = 0.f, zpyv = 0.f;
    if (tid < 64){ zpxv = zg[tid]; zpyv = zb[tid] + g_Pz[b*64 + tid]; }
    float ngA = nag[lane], ngB = nag[lane+32];
    float nbA = nab[lane], nbB = nab[lane+32];

    // exclusive prefix over prior chunks' partials -> packed A2
    ull A2[8];
    float zc = 0.f;
    {
        float A[16];
        #pragma unroll
        for (int i = 0; i < 16; i++) A[i] = 0.f;
        for (int c2 = 0; c2 < ch; c2++){
            const float* gp = &g_part[(size_t)(b*NCH + c2) * 4160];
            #pragma unroll
            for (int i = 0; i < 16; i++) A[i] += gp[(d0 + i)*64 + p];
            if (tid < 64) zc += gp[4096 + tid];
        }
        #pragma unroll
        for (int j = 0; j < 8; j++) A2[j] = pack2(A[2*j], A[2*j+1]);
    }

    // per-CTA constants (one block reduce)
    float Cwx, Cwx2, Cwxwy, Cwy, Cwy2, Czpx2, Czpxzpy, Czpy2;
    {
        ull c0p = 0ull, c1p = 0ull, c2p = 0ull, c3p = 0ull, c4p = 0ull;
        #pragma unroll
        for (int j = 0; j < 8; j++){
            c0p = fadd2(c0p, wx2[j]);
            c1p = ffma2(wx2[j], wx2[j], c1p);
            c2p = ffma2(wx2[j], wy2[j], c2p);
            c3p = fadd2(c3p, wy2[j]);
            c4p = ffma2(wy2[j], wy2[j], c4p);
        }
        float cv[8];
        cv[0] = hsum2(c0p); cv[1] = hsum2(c1p); cv[2] = hsum2(c2p);
        cv[3] = hsum2(c3p); cv[4] = hsum2(c4p);
        cv[5] = zpxv*zpxv; cv[6] = zpxv*zpyv; cv[7] = zpyv*zpyv;  // 0 for tid>=64
        #pragma unroll
        for (int k = 0; k < 8; k++){
            #pragma unroll
            for (int o = 16; o; o >>= 1) cv[k] += __shfl_xor_sync(0xffffffffu, cv[k], o);
        }
        if (lane == 0){
            #pragma unroll
            for (int k = 0; k < 8; k++) cred[w*8 + k] = cv[k];
        }
        __syncthreads();
        float s[8];
        #pragma unroll
        for (int k = 0; k < 8; k++){
            float t = 0.f;
            #pragma unroll
            for (int w2 = 0; w2 < 8; w2++) t += cred[w2*8 + k];
            s[k] = t;
        }
        Cwx=s[0]; Cwx2=s[1]; Cwxwy=s[2]; Cwy=s[3]; Cwy2=s[4];
        Czpx2=s[5]; Czpxzpy=s[6]; Czpy2=s[7];
    }
    const float inv4096 = 1.f/4096.f, inv64 = 1.f/64.f;

    // ================= PASS 1: moments (packed), no syncs =================
    #pragma unroll 1
    for (int r = 0; r < CHUNK; r++){
        const ulonglong2* z2p = (const ulonglong2*)&ztile[r*64 + d0];
        float vv = vtile[r*64 + p];
        ull vv2 = pack2(vv, vv);
        ull pS = 0ull, pS2 = 0ull, pU = 0ull, pU2 = 0ull, pUwx = 0ull, pUwy = 0ull;
        #pragma unroll
        for (int j4 = 0; j4 < 4; j4++){
            ulonglong2 zz = z2p[j4];
            #pragma unroll
            for (int c = 0; c < 2; c++){
                int j = j4*2 + c;
                ull zp = c ? zz.y : zz.x;
                A2[j] = ffma2(zp, vv2, A2[j]);
                pS  = fadd2(pS, A2[j]);
                pS2 = ffma2(A2[j], A2[j], pS2);
                ull uu = fmul2(A2[j], wx2[j]);
                pU   = fadd2(pU, uu);
                pU2  = ffma2(uu, uu, pU2);
                pUwx = ffma2(uu, wx2[j], pUwx);
                pUwy = ffma2(uu, wy2[j], pUwy);
            }
        }
        float sA = hsum2(pS),  sA2 = hsum2(pS2), sU = hsum2(pU);
        float sU2 = hsum2(pU2), sUwx = hsum2(pUwx), sUwy = hsum2(pUwy);

        float r6 = 0.f, r7 = 0.f, r8 = 0.f, r9 = 0.f, r10 = 0.f, r11 = 0.f;
        if (tid < 64){
            zc += ztile[r*64 + tid];
            float qv = qtile[r*64 + tid];
            float y = zc * zpxv;
            r6 = zc; r7 = zc*zc; r8 = y*y; r9 = y*zpyv; r10 = y*zpxv; r11 = qv*qv;
        }
        #pragma unroll
        for (int o = 16; o; o >>= 1){
            sA   += __shfl_xor_sync(0xffffffffu, sA, o);
            sA2  += __shfl_xor_sync(0xffffffffu, sA2, o);
            sU   += __shfl_xor_sync(0xffffffffu, sU, o);
            sU2  += __shfl_xor_sync(0xffffffffu, sU2, o);
            sUwx += __shfl_xor_sync(0xffffffffu, sUwx, o);
            sUwy += __shfl_xor_sync(0xffffffffu, sUwy, o);
        }
        if (w < 2){
            #pragma unroll
            for (int o = 16; o; o >>= 1){
                r6  += __shfl_xor_sync(0xffffffffu, r6, o);
                r7  += __shfl_xor_sync(0xffffffffu, r7, o);
                r8  += __shfl_xor_sync(0xffffffffu, r8, o);
                r9  += __shfl_xor_sync(0xffffffffu, r9, o);
                r10 += __shfl_xor_sync(0xffffffffu, r10, o);
                r11 += __shfl_xor_sync(0xffffffffu, r11, o);
            }
        }
        if (lane == 0){
            int mbase = (r*8 + w)*3;
            mom4[mbase + 0] = make_float4(sA, sA2, sU, sU2);
            mom4[mbase + 1] = make_float4(sUwx, sUwy, r6, r7);
            mom4[mbase + 2] = make_float4(r8, r9, r10, r11);
        }
    }
    __syncthreads();

    // ================= SCALAR PHASE: thread tid<32 owns step tid ==========
    if (tid < 32){
        int r = tid;
        float4 a0 = make_float4(0,0,0,0), a1 = a0, a2v = a0;
        #pragma unroll
        for (int w2 = 0; w2 < 8; w2++){
            int mbase = (r*8 + w2)*3;
            float4 t0 = mom4[mbase], t1 = mom4[mbase+1], t2 = mom4[mbase+2];
            a0.x += t0.x; a0.y += t0.y; a0.z += t0.z; a0.w += t0.w;
            a1.x += t1.x; a1.y += t1.y; a1.z += t1.z; a1.w += t1.w;
            a2v.x += t2.x; a2v.y += t2.y; a2v.z += t2.z; a2v.w += t2.w;
        }
        float aBar = a0.x * inv4096;
        float ivs  = rsqrtf(a0.y*inv4096 - aBar*aBar + LN_EPS);
        float c0   = aBar * ivs;
        float Sst  = ivs*a0.z - c0*Cwx + Cwy;
        float Sst2 = ivs*ivs*a0.w + 2.f*ivs*(a1.y - c0*a1.x)
                   + Cwy2 - 2.f*c0*Cwxwy + c0*c0*Cwx2;
        float mzv  = a1.z * inv64;
        float ivz  = rsqrtf(a1.w*inv64 - mzv*mzv + LN_EPS);
        float dd0  = mzv * ivz;
        float Szt2 = ivz*ivz*a2v.x + 2.f*ivz*(a2v.y - dd0*a2v.z)
                   + Czpy2 - 2.f*dd0*Czpxzpy + dd0*dd0*Czpx2;
        float zn   = fmaxf(sqrtf(Szt2), 1e-8f);
        float izn  = 1.f / zn;
        float mst  = Sst * inv4096;
        float mnam = mst * izn;
        float vnam = (Sst2*inv4096 - mst*mst) * izn * izn;
        float ivn  = rsqrtf(vnam + LN_EPS);
        float k1   = izn * ivn, k0 = -mnam * ivn;
        float srq  = 1.f / fmaxf(sqrtf(a2v.w), 1e-8f);
        float f1 = k1 * ivs, f2 = -f1 * aBar, f3 = k1;
        scal4[r*2 + 0] = make_float4(f1, f2, f3, k0);
        scal4[r*2 + 1] = make_float4(srq, mzv, ivz, 0.f);
    }
    __syncthreads();

    // ================= PASS 2: backward (packed), no syncs =================
    float fsum = 0.f, fsq = 0.f;
    #pragma unroll 1
    for (int r = CHUNK - 1; r >= 0; r--){
        float4 s0 = scal4[r*2 + 0];
        ull f1p = pack2(s0.x, s0.x), f2p = pack2(s0.y, s0.y);
        ull f3p = pack2(s0.z, s0.z), k0p = pack2(s0.w, s0.w);
        const ulonglong2* z2p = (const ulonglong2*)&ztile[r*64 + d0];
        const ulonglong2* q2p = (const ulonglong2*)&qtile[r*64 + d0];
        float vv = vtile[r*64 + p];
        ull nvv2 = pack2(-vv, -vv);
        ull pacc = 0ull;
        #pragma unroll
        for (int j4 = 0; j4 < 4; j4++){
            ulonglong2 zz = z2p[j4];
            ulonglong2 qq = q2p[j4];
            #pragma unroll
            for (int c = 0; c < 2; c++){
                int j = j4*2 + c;
                ull zp = c ? zz.y : zz.x;
                ull qp = c ? qq.y : qq.x;
                ull uu = fmul2(A2[j], wx2[j]);
                ull aa = ffma2(f1p, uu, k0p);
                aa = ffma2(f2p, wx2[j], aa);
                aa = ffma2(f3p, wy2[j], aa);
                ull t = ffma2(aa, wz2[j], ww2[j]);
                pacc = ffma2(qp, t, pacc);
                A2[j] = ffma2(zp, nvv2, A2[j]);    // step back to A_{r-1}
            }
        }
        na_s[r*256 + tid] = hsum2(pacc);
        if (tid < 64){
            float4 s1 = scal4[r*2 + 1];
            float zt = (zc - s1.y)*s1.z*zpxv + zpyv;
            float rr = qtile[r*64 + tid] / fmaxf(zt, 1e-6f);
            fsum += rr; fsq = fmaf(rr, rr, fsq);
            zc -= ztile[r*64 + tid];
        }
    }
    // per-CTA std partials (deterministic, no atomics on values)
    if (tid < 64){
        float s1 = fsum, s2 = fsq;
        #pragma unroll
        for (int o = 16; o; o >>= 1){
            s1 += __shfl_xor_sync(0xffffffffu, s1, o);
            s2 += __shfl_xor_sync(0xffffffffu, s2, o);
        }
        if (lane == 0){ db[(tid>>5)*2] = (double)s1; db[(tid>>5)*2 + 1] = (double)s2; }
    }
    __syncthreads();
    if (tid == 0){
        g_std[pid*2 + 0] = db[0] + db[2];
        g_std[pid*2 + 1] = db[1] + db[3];
        __threadfence();
        unsigned int old = atomicAdd(&g_cnt, 1u);
        sIsLast = ((old % (unsigned)nStd) == (unsigned)(nStd - 1)) ? 1 : 0;
    }
    __syncthreads();

    // ================= EPILOGUE: warp w -> steps w*4 .. w*4+3 ==============
    #pragma unroll
    for (int rr = 0; rr < 4; rr++){
        int r = w*4 + rr;
        float srq = scal4[r*2 + 1].x;
        const float* np = &na_s[r*256];
        float nvA = (np[lane] + np[lane+64] + np[lane+128] + np[lane+192]) * srq;
        float nvB = (np[lane+32] + np[lane+96] + np[lane+160] + np[lane+224]) * srq;
        float s1 = nvA + nvB, s2 = nvA*nvA + nvB*nvB;
        #pragma unroll
        for (int o = 16; o; o >>= 1){
            s1 += __shfl_xor_sync(0xffffffffu, s1, o);
            s2 += __shfl_xor_sync(0xffffffffu, s2, o);
        }
        float mn = s1 * inv64;
        float iv = rsqrtf(s2*inv64 - mn*mn + LN_EPS);
        float* op = out + xbase + (size_t)r*64;
        op[lane]      = (nvA - mn)*iv*ngA + nbA;
        op[lane + 32] = (nvB - mn)*iv*ngB + nbB;
    }

    // ================= LAST CTA: finalize std in-kernel ====================
    if (sIsLast){
        __threadfence();   // acquire all g_std writes
        double a = 0.0, c = 0.0;
        if (tid < nStd){ a = g_std[tid*2]; c = g_std[tid*2 + 1]; }
        #pragma unroll
        for (int o = 16; o; o >>= 1){
            a += __shfl_xor_sync(0xffffffffu, a, o);
            c += __shfl_xor_sync(0xffffffffu, c, o);
        }
        if (lane == 0){ sred[w*2] = a; sred[w*2 + 1] = c; }
        __syncthreads();
        if (tid == 0){
            double sa = 0.0, sc = 0.0;
            #pragma unroll
            for (int w2 = 0; w2 < 8; w2++){ sa += sred[w2*2]; sc += sred[w2*2 + 1]; }
            int n = nStd * CHUNK * 64;
            double mean = sa / (double)n;
            double var  = (sc - sa*mean) / (double)(n - 1);
            out[outpos] = (float)sqrt(var);
        }
    }
}

// ---------------- launch ----------------
extern "C" void kernel_launch(void* const* d_in, const int* in_sizes, int n_in,
                              void* d_out, int out_size)
{
    const int*   uid   = (const int*)  d_in[0];
    const float* X     = (const float*)d_in[1];
    const float* Pm    = (const float*)d_in[2];
    const float* Sm    = (const float*)d_in[3];
    const float* Wq    = (const float*)d_in[4];
    const float* bq    = (const float*)d_in[5];
    const float* Wk    = (const float*)d_in[6];
    const float* bk    = (const float*)d_in[7];
    const float* Wv    = (const float*)d_in[8];
    const float* bv    = (const float*)d_in[9];
    const float* zg    = (const float*)d_in[10];
    const float* zb    = (const float*)d_in[11];
    const float* sg    = (const float*)d_in[12];
    const float* sb    = (const float*)d_in[13];
    const float* ng    = (const float*)d_in[14];
    const float* nb    = (const float*)d_in[15];
    const float* nag   = (const float*)d_in[16];
    const float* nab   = (const float*)d_in[17];
    const float* pzbuf = (const float*)d_in[18];
    const float* psbuf = (const float*)d_in[19];
    float* out = (float*)d_out;

    int B   = in_sizes[0];
    int L   = in_sizes[1] / (B * 64);
    int NCH = L / CHUNK;
    int LP  = in_sizes[2] / (B * 64);
    int NPH = B * NCH;

    size_t smAll = (size_t)SM_TOTAL * 4;   // ~71 KB dynamic
    cudaFuncSetAttribute(k_all, cudaFuncAttributeMaxDynamicSharedMemorySize, (int)smAll);

    k_all<<<B + NPH, 256, smAll>>>(uid, X, Pm, Sm, Wq, bq, Wk, bk, Wv, bv,
                                   zg, zb, sg, sb, ng, nb, nag, nab,
                                   pzbuf, psbuf, out, NCH, LP, B,
                                   NPH, out_size - 1);
}

// round 17
// speedup vs baseline: 1.6737x; 1.1307x over previous
#include <cuda_runtime.h>
#include <math.h>

#define EPS 1e-8f
#define LN_EPS 1e-5f
#define CHUNK 32

typedef unsigned long long ull;

// ---------------- packed f32x2 helpers (sm_103a) ----------------
__device__ __forceinline__ ull pack2(float lo, float hi){
    ull r; asm("mov.b64 %0, {%1,%2};" : "=l"(r) : "f"(lo), "f"(hi)); return r;
}
__device__ __forceinline__ void unpack2(ull v, float &lo, float &hi){
    asm("mov.b64 {%0,%1}, %2;" : "=f"(lo), "=f"(hi) : "l"(v));
}
__device__ __forceinline__ ull ffma2(ull a, ull b, ull c){
    ull d; asm("fma.rn.f32x2 %0, %1, %2, %3;" : "=l"(d) : "l"(a), "l"(b), "l"(c)); return d;
}
__device__ __forceinline__ ull fmul2(ull a, ull b){
    ull d; asm("mul.rn.f32x2 %0, %1, %2;" : "=l"(d) : "l"(a), "l"(b)); return d;
}
__device__ __forceinline__ ull fadd2(ull a, ull b){
    ull d; asm("add.rn.f32x2 %0, %1, %2;" : "=l"(d) : "l"(a), "l"(b)); return d;
}
__device__ __forceinline__ float hsum2(ull v){ float lo, hi; unpack2(v, lo, hi); return lo + hi; }

// packed-pair warp butterfly: reduces TWO f32 sums at 3 instr/level
// (2x SHFL.32 + 1x FADD2) instead of 4. All 32 lanes must participate.
__device__ __forceinline__ ull redsum2(ull v){
    #pragma unroll
    for (int o = 16; o; o >>= 1)
        v = fadd2(v, __shfl_xor_sync(0xffffffffu, v, o));
    return v;
}
// scalar warp sum (5-level shfl)
__device__ __forceinline__ float redsum(float x){
    #pragma unroll
    for (int o = 16; o; o >>= 1) x += __shfl_xor_sync(0xffffffffu, x, o);
    return x;
}

// ---------------- scratch (static __device__, no allocs) ----------------
__device__ __align__(16) float  g_part[16*16*4160];
__device__ float4 g_pack[16*4096];      // {wx=sg, wy=sb+Ps_ln, wz=ng, ww=nb+Mprev_ln}
__device__ float  g_Pz[16*64];          // P_z_ln last step per batch
__device__ double g_std[1024];          // per-chunk-CTA {sum, sumsq}
__device__ volatile int g_fp[64];       // prompt-ready flags (per batch)
__device__ volatile int g_fc[1024];     // chunk-partials-ready flags (per chunk CTA)
__device__ unsigned int g_cnt;          // monotonic completion counter (never reset)

__device__ __forceinline__ float eluf(float x){ return x > 0.f ? x : (expf(x) - 1.f); }

// one-sync block reduce for 256 threads (8 warps), 2 values packed.
__device__ __forceinline__ void block_reduce_2p(float v0, float v1, float* red,
                                                float &o0, float &o1){
    int lane = threadIdx.x & 31, w = threadIdx.x >> 5;
    ull s = redsum2(pack2(v0, v1));
    if (lane == 0){ float a, b; unpack2(s, a, b); red[w*2] = a; red[w*2+1] = b; }
    __syncthreads();
    float a = 0.f, b = 0.f;
    #pragma unroll
    for (int w2 = 0; w2 < 8; w2++){ a += red[w2*2]; b += red[w2*2+1]; }
    o0 = a; o1 = b;
}
// one-sync block reduce, 1 value
__device__ __forceinline__ float block_reduce_1(float v, float* red){
    int lane = threadIdx.x & 31, w = threadIdx.x >> 5;
    float x = redsum(v);
    if (lane == 0) red[w] = x;
    __syncthreads();
    float s = 0.f;
    #pragma unroll
    for (int w2 = 0; w2 < 8; w2++) s += red[w2];
    return s;
}

// smem layout constants for the chunk branch (floats)
#define SM_Z     0        // 2048
#define SM_V     2048     // 2048
#define SM_Q     4096     // 2048
#define SM_MOM   6144     // 3072 (32 steps * 8 warps * 3 float4)
#define SM_SCAL  9216     // 256  (32 * 2 float4)
#define SM_NAS   9472     // 8192 (aliases xsT during GEMV)
#define SM_XST   9472     // 2304 (64*36)
#define SM_CRED  17664    // 64
#define SM_DB    17728    // 8 (double[4])
#define SM_TOTAL 17736

// ================= fused kernel: prompt CTAs [0,B), chunk CTAs [B, B+B*NCH) ==
__global__ __launch_bounds__(256, 2)
void k_all(const int* uid, const float* X, const float* Pm, const float* Sm,
           const float* Wq, const float* bq, const float* Wk, const float* bk,
           const float* Wv, const float* bv,
           const float* zg, const float* zb, const float* sg, const float* sb,
           const float* ng, const float* nb,
           const float* nag, const float* nab,
           const float* pzbuf, const float* psbuf,
           float* out, int NCH, int LP, int B, int nStd, int outpos)
{
    extern __shared__ __align__(16) float SM[];
    __shared__ int sIsLast;
    __shared__ double sred[64];
    int tid = threadIdx.x;
    int bi = blockIdx.x;
    int lane = tid & 31, w = tid >> 5;

    if (bi < B){
        // ================ prompt branch ================
        float* xsA  = SM;          float* xsB  = SM + 512;
        float* zbA  = SM + 1024;   float* zbB  = SM + 1536;
        float* vbA  = SM + 2048;   float* vbB  = SM + 2560;
        float* bufA = SM + 3072;   float* bufB = SM + 7168;
        float* zl   = SM + 11264;
        float* redA = SM + 11328;  float* redB = SM + 11344;

        int b = bi;
        int p = tid & 63, d0 = (tid >> 6) * 16;

        for (int i = tid; i < 512; i += 256){ xsA[i] = 0.f; xsB[i] = 0.f; }
        for (int i = tid; i < LP*64; i += 256){
            xsA[i] = Pm[b*LP*64 + i];
            xsB[i] = Sm[b*LP*64 + i];
        }
        __syncthreads();

        {
            int pass = tid >> 7, dt = (tid >> 6) & 1, col = tid & 63;
            const float* xp = pass ? xsB : xsA;
            float* zp = pass ? zbB : zbA;
            float* vp = pass ? vbB : vbA;
            const float* W  = dt ? Wv : Wk;
            float bb = dt ? bv[col] : bk[col];
            float acc8[8];
            #pragma unroll
            for (int l = 0; l < 8; l++) acc8[l] = bb;
            #pragma unroll 4
            for (int k = 0; k < 64; k++){
                float wv2 = W[k*64 + col];
                #pragma unroll
                for (int l = 0; l < 8; l++) acc8[l] += xp[l*64 + k] * wv2;
            }
            if (dt == 0){
                #pragma unroll
                for (int l = 0; l < 8; l++) zp[l*64 + col] = eluf(acc8[l]);
            } else {
                #pragma unroll
                for (int l = 0; l < 8; l++) vp[l*64 + col] = acc8[l];
            }
        }
        __syncthreads();

        float accP[16], accS[16];
        #pragma unroll
        for (int i = 0; i < 16; i++){ accP[i] = 0.f; accS[i] = 0.f; }
        for (int l = 0; l < LP; l++){
            float vvP = vbA[l*64 + p], vvS = vbB[l*64 + p];
            #pragma unroll
            for (int i = 0; i < 16; i++){
                accP[i] += zbA[l*64 + d0 + i] * vvP;
                accS[i] += zbB[l*64 + d0 + i] * vvS;
            }
        }
        float zsP = 0.f, zsS = 0.f;
        if (tid < 64){
            for (int l = 0; l < LP; l++){ zsP += zbA[l*64 + tid]; zsS += zbB[l*64 + tid]; }
        }

        float o0, o1;
        block_reduce_2p((tid < 64) ? zsP : 0.f, (tid < 64) ? zsP*zsP : 0.f, redA, o0, o1);
        {
            float mz = o0*(1.f/64.f);
            float ivz = rsqrtf(o1*(1.f/64.f) - mz*mz + LN_EPS);
            if (tid < 64) g_Pz[b*64 + tid] = (zsP - mz)*ivz*zg[tid] + zb[tid];
        }
        __syncthreads();
        block_reduce_2p((tid < 64) ? zsS : 0.f, (tid < 64) ? zsS*zsS : 0.f, redB, o0, o1);
        {
            float mz = o0*(1.f/64.f);
            float ivz = rsqrtf(o1*(1.f/64.f) - mz*mz + LN_EPS);
            if (tid < 64) zl[tid] = (zsS - mz)*ivz*zg[tid] + zb[tid];
        }
        __syncthreads();
        float sv0 = 0.f, sv1 = 0.f;
        #pragma unroll
        for (int i = 0; i < 16; i++){ sv0 += accP[i]; sv1 += accP[i]*accP[i]; }
        block_reduce_2p(sv0, sv1, redA, o0, o1);
        {
            float ms = o0*(1.f/4096.f);
            float ivs = rsqrtf(o1*(1.f/4096.f) - ms*ms + LN_EPS);
            #pragma unroll
            for (int i = 0; i < 16; i++){
                int e = (d0 + i)*64 + p;
                bufA[e] = (accP[i] - ms)*ivs*sg[e] + sb[e];
            }
        }
        __syncthreads();
        sv0 = 0.f; sv1 = 0.f;
        #pragma unroll
        for (int i = 0; i < 16; i++){ sv0 += accS[i]; sv1 += accS[i]*accS[i]; }
        block_reduce_2p(sv0, sv1, redB, o0, o1);
        {
            float ms = o0*(1.f/4096.f);
            float ivs = rsqrtf(o1*(1.f/4096.f) - ms*ms + LN_EPS);
            #pragma unroll
            for (int i = 0; i < 16; i++){
                int e = (d0 + i)*64 + p;
                bufB[e] = (accS[i] - ms)*ivs*sg[e] + sb[e];
            }
        }
        __syncthreads();

        int u = uid[b];
        float pzv = 0.f;
        if (tid < 64) pzv = pzbuf[(size_t)u*64 + tid] + zl[tid];
        float n2 = block_reduce_1((tid < 64) ? pzv*pzv : 0.f, redA);
        float ipn = 1.f / (fmaxf(sqrtf(n2), 1e-8f) + EPS);
        __syncthreads();

        float pn16[16];
        sv0 = 0.f; sv1 = 0.f;
        #pragma unroll
        for (int k2 = 0; k2 < 16; k2++){
            int e = tid + k2*256;
            float pv = (psbuf[(size_t)u*4096 + e] + bufB[e]) * ipn;
            pn16[k2] = pv; sv0 += pv; sv1 += pv*pv;
        }
        block_reduce_2p(sv0, sv1, redB, o0, o1);
        float mp = o0*(1.f/4096.f);
        float ivp = rsqrtf(o1*(1.f/4096.f) - mp*mp + LN_EPS);
        #pragma unroll
        for (int k2 = 0; k2 < 16; k2++){
            int e = tid + k2*256;
            float M = (pn16[k2] - mp)*ivp*ng[e] + nb[e];
            g_pack[b*4096 + e] = make_float4(sg[e], sb[e] + bufA[e], ng[e], nb[e] + M);
        }
        // publish prompt results
        __threadfence();
        __syncthreads();
        if (tid == 0) g_fp[b] = 1;
        return;
    }

    // ================ chunk branch ================
    float*  ztile = SM + SM_Z;
    float*  vtile = SM + SM_V;
    float*  qtile = SM + SM_Q;
    float4* mom4  = (float4*)(SM + SM_MOM);
    float4* scal4 = (float4*)(SM + SM_SCAL);
    float*  na_s  = SM + SM_NAS;
    float*  xsT   = SM + SM_XST;       // aliases na_s (GEMV phase only)
    float*  cred  = SM + SM_CRED;
    double* db    = (double*)(SM + SM_DB);

    int pid = bi - B;
    int b = pid / NCH, ch = pid % NCH;
    int p = tid & 63, d0 = (tid >> 6) * 16;
    int L = NCH * CHUNK;
    size_t xbase = ((size_t)b*L + (size_t)ch*CHUNK) * 64;

    // ---- GEMV phase: load+transpose X, compute q/z/v straight into smem ----
    #pragma unroll
    for (int i = 0; i < 8; i++){
        int e = tid + i*256;
        int l = e >> 6, k = e & 63;
        xsT[k*36 + l] = X[xbase + e];
    }
    __syncthreads();

    if (tid < 192){
        int dt = tid >> 6, col = tid & 63;
        const float* W = (dt == 0) ? Wq : ((dt == 1) ? Wk : Wv);
        float bb = (dt == 0) ? bq[col] : ((dt == 1) ? bk[col] : bv[col]);
        ull bb2 = pack2(bb, bb);
        ull acc2[16];
        #pragma unroll
        for (int j = 0; j < 16; j++) acc2[j] = bb2;
        #pragma unroll 4
        for (int k = 0; k < 64; k++){
            float wv2 = W[k*64 + col];
            ull wp = pack2(wv2, wv2);
            const ulonglong2* xr = (const ulonglong2*)&xsT[k*36];
            #pragma unroll
            for (int j4 = 0; j4 < 8; j4++){
                ulonglong2 xx = xr[j4];
                acc2[j4*2+0] = ffma2(xx.x, wp, acc2[j4*2+0]);
                acc2[j4*2+1] = ffma2(xx.y, wp, acc2[j4*2+1]);
            }
        }
        float* dst = (dt == 0) ? qtile : ((dt == 1) ? ztile : vtile);
        if (dt == 2){
            #pragma unroll
            for (int j = 0; j < 16; j++){
                float a, b2; unpack2(acc2[j], a, b2);
                dst[(2*j  )*64 + col] = a;
                dst[(2*j+1)*64 + col] = b2;
            }
        } else {
            #pragma unroll
            for (int j = 0; j < 16; j++){
                float a, b2; unpack2(acc2[j], a, b2);
                dst[(2*j  )*64 + col] = eluf(a);
                dst[(2*j+1)*64 + col] = eluf(b2);
            }
        }
    }
    __syncthreads();

    // ---- own-chunk partial sums -> g_part, publish flag ----
    {
        ull acc2o[8];
        #pragma unroll
        for (int j = 0; j < 8; j++) acc2o[j] = 0ull;
        #pragma unroll 4
        for (int l = 0; l < 32; l++){
            float vv = vtile[l*64 + p];
            ull vvp = pack2(vv, vv);
            const ulonglong2* zb2p = (const ulonglong2*)&ztile[l*64 + d0];
            #pragma unroll
            for (int j4 = 0; j4 < 4; j4++){
                ulonglong2 zz = zb2p[j4];
                acc2o[j4*2+0] = ffma2(zz.x, vvp, acc2o[j4*2+0]);
                acc2o[j4*2+1] = ffma2(zz.y, vvp, acc2o[j4*2+1]);
            }
        }
        size_t o = (size_t)pid * 4160;
        #pragma unroll
        for (int j = 0; j < 8; j++){
            float a, b2; unpack2(acc2o[j], a, b2);
            g_part[o + (d0 + 2*j  )*64 + p] = a;
            g_part[o + (d0 + 2*j+1)*64 + p] = b2;
        }
        if (tid < 64){
            float zs = 0.f;
            #pragma unroll 4
            for (int l = 0; l < 32; l++) zs += ztile[l*64 + tid];
            g_part[o + 4096 + tid] = zs;
        }
        __threadfence();
        __syncthreads();
        if (tid == 0) g_fc[pid] = 1;
    }

    // ---- wait for prompt results, then prefix partials ----
    if (tid == 0){
        while (g_fp[b] == 0) __nanosleep(64);
        for (int c2 = 0; c2 < ch; c2++)
            while (g_fc[b*NCH + c2] == 0) __nanosleep(64);
    }
    __syncthreads();
    __threadfence();

    // packed constants -> registers
    ull wx2[8], wy2[8], wz2[8], ww2[8];
    {
        const float4* pk = &g_pack[b*4096];
        #pragma unroll
        for (int j = 0; j < 8; j++){
            float4 ta = pk[(d0 + 2*j    )*64 + p];
            float4 tb = pk[(d0 + 2*j + 1)*64 + p];
            wx2[j] = pack2(ta.x, tb.x);
            wy2[j] = pack2(ta.y, tb.y);
            wz2[j] = pack2(ta.z, tb.z);
            ww2[j] = pack2(ta.w, tb.w);
        }
    }
    float zpxv = 0.f, zpyv = 0.f;
    if (tid < 64){ zpxv = zg[tid]; zpyv = zb[tid] + g_Pz[b*64 + tid]; }
    float ngA = nag[lane], ngB = nag[lane+32];
    float nbA = nab[lane], nbB = nab[lane+32];

    // exclusive prefix over prior chunks' partials -> packed A2
    ull A2[8];
    float zc = 0.f;
    {
        float A[16];
        #pragma unroll
        for (int i = 0; i < 16; i++) A[i] = 0.f;
        for (int c2 = 0; c2 < ch; c2++){
            const float* gp = &g_part[(size_t)(b*NCH + c2) * 4160];
            #pragma unroll
            for (int i = 0; i < 16; i++) A[i] += gp[(d0 + i)*64 + p];
            if (tid < 64) zc += gp[4096 + tid];
        }
        #pragma unroll
        for (int j = 0; j < 8; j++) A2[j] = pack2(A[2*j], A[2*j+1]);
    }

    // per-CTA constants (one block reduce)
    float Cwx, Cwx2, Cwxwy, Cwy, Cwy2, Czpx2, Czpxzpy, Czpy2;
    {
        ull c0p = 0ull, c1p = 0ull, c2p = 0ull, c3p = 0ull, c4p = 0ull;
        #pragma unroll
        for (int j = 0; j < 8; j++){
            c0p = fadd2(c0p, wx2[j]);
            c1p = ffma2(wx2[j], wx2[j], c1p);
            c2p = ffma2(wx2[j], wy2[j], c2p);
            c3p = fadd2(c3p, wy2[j]);
            c4p = ffma2(wy2[j], wy2[j], c4p);
        }
        // pack 8 scalars into 4 pair-reduces
        ull m01 = redsum2(pack2(hsum2(c0p), hsum2(c1p)));
        ull m23 = redsum2(pack2(hsum2(c2p), hsum2(c3p)));
        ull m45 = redsum2(pack2(hsum2(c4p), zpxv*zpxv));
        ull m67 = redsum2(pack2(zpxv*zpyv, zpyv*zpyv));
        if (lane == 0){
            float a, b2;
            unpack2(m01, a, b2); cred[w*8 + 0] = a; cred[w*8 + 1] = b2;
            unpack2(m23, a, b2); cred[w*8 + 2] = a; cred[w*8 + 3] = b2;
            unpack2(m45, a, b2); cred[w*8 + 4] = a; cred[w*8 + 5] = b2;
            unpack2(m67, a, b2); cred[w*8 + 6] = a; cred[w*8 + 7] = b2;
        }
        __syncthreads();
        float s[8];
        #pragma unroll
        for (int k = 0; k < 8; k++){
            float t = 0.f;
            #pragma unroll
            for (int w2 = 0; w2 < 8; w2++) t += cred[w2*8 + k];
            s[k] = t;
        }
        Cwx=s[0]; Cwx2=s[1]; Cwxwy=s[2]; Cwy=s[3]; Cwy2=s[4];
        Czpx2=s[5]; Czpxzpy=s[6]; Czpy2=s[7];
    }
    const float inv4096 = 1.f/4096.f, inv64 = 1.f/64.f;

    // ================= PASS 1: moments (packed math + packed reduces) ======
    #pragma unroll 1
    for (int r = 0; r < CHUNK; r++){
        const ulonglong2* z2p = (const ulonglong2*)&ztile[r*64 + d0];
        float vv = vtile[r*64 + p];
        ull vv2 = pack2(vv, vv);
        ull pS = 0ull, pS2 = 0ull, pU = 0ull, pU2 = 0ull, pUwx = 0ull, pUwy = 0ull;
        #pragma unroll
        for (int j4 = 0; j4 < 4; j4++){
            ulonglong2 zz = z2p[j4];
            #pragma unroll
            for (int c = 0; c < 2; c++){
                int j = j4*2 + c;
                ull zp = c ? zz.y : zz.x;
                A2[j] = ffma2(zp, vv2, A2[j]);
                pS  = fadd2(pS, A2[j]);
                pS2 = ffma2(A2[j], A2[j], pS2);
                ull uu = fmul2(A2[j], wx2[j]);
                pU   = fadd2(pU, uu);
                pU2  = ffma2(uu, uu, pU2);
                pUwx = ffma2(uu, wx2[j], pUwx);
                pUwy = ffma2(uu, wy2[j], pUwy);
            }
        }
        // 3 packed pair-reduces for the 6 moments
        ull mA = redsum2(pack2(hsum2(pS),   hsum2(pS2)));
        ull mU = redsum2(pack2(hsum2(pU),   hsum2(pU2)));
        ull mW = redsum2(pack2(hsum2(pUwx), hsum2(pUwy)));

        if (w < 2){
            float r6 = 0.f, r7 = 0.f, r8 = 0.f, r9 = 0.f, r10 = 0.f, r11 = 0.f;
            if (tid < 64){
                zc += ztile[r*64 + tid];
                float qv = qtile[r*64 + tid];
                float y = zc * zpxv;
                r6 = zc; r7 = zc*zc; r8 = y*y; r9 = y*zpyv; r10 = y*zpxv; r11 = qv*qv;
            }
            ull m67v  = redsum2(pack2(r6, r7));
            ull m89v  = redsum2(pack2(r8, r9));
            ull m1011 = redsum2(pack2(r10, r11));
            if (lane == 0){
                int mbase = (r*8 + w)*3;
                float a, b2, c2, dd;
                unpack2(mW, a, b2); unpack2(m67v, c2, dd);
                mom4[mbase + 1] = make_float4(a, b2, c2, dd);
                unpack2(m89v, a, b2); unpack2(m1011, c2, dd);
                mom4[mbase + 2] = make_float4(a, b2, c2, dd);
            }
        } else {
            if (lane == 0){
                int mbase = (r*8 + w)*3;
                float a, b2; unpack2(mW, a, b2);
                mom4[mbase + 1] = make_float4(a, b2, 0.f, 0.f);
                mom4[mbase + 2] = make_float4(0.f, 0.f, 0.f, 0.f);
            }
        }
        if (lane == 0){
            int mbase = (r*8 + w)*3;
            float a, b2, c2, dd;
            unpack2(mA, a, b2); unpack2(mU, c2, dd);
            mom4[mbase + 0] = make_float4(a, b2, c2, dd);
        }
    }
    __syncthreads();

    // ================= SCALAR PHASE: thread tid<32 owns step tid ==========
    if (tid < 32){
        int r = tid;
        float4 a0 = make_float4(0,0,0,0), a1 = a0, a2v = a0;
        #pragma unroll
        for (int w2 = 0; w2 < 8; w2++){
            int mbase = (r*8 + w2)*3;
            float4 t0 = mom4[mbase], t1 = mom4[mbase+1], t2 = mom4[mbase+2];
            a0.x += t0.x; a0.y += t0.y; a0.z += t0.z; a0.w += t0.w;
            a1.x += t1.x; a1.y += t1.y; a1.z += t1.z; a1.w += t1.w;
            a2v.x += t2.x; a2v.y += t2.y; a2v.z += t2.z; a2v.w += t2.w;
        }
        float aBar = a0.x * inv4096;
        float ivs  = rsqrtf(a0.y*inv4096 - aBar*aBar + LN_EPS);
        float c0   = aBar * ivs;
        float Sst  = ivs*a0.z - c0*Cwx + Cwy;
        float Sst2 = ivs*ivs*a0.w + 2.f*ivs*(a1.y - c0*a1.x)
                   + Cwy2 - 2.f*c0*Cwxwy + c0*c0*Cwx2;
        float mzv  = a1.z * inv64;
        float ivz  = rsqrtf(a1.w*inv64 - mzv*mzv + LN_EPS);
        float dd0  = mzv * ivz;
        float Szt2 = ivz*ivz*a2v.x + 2.f*ivz*(a2v.y - dd0*a2v.z)
                   + Czpy2 - 2.f*dd0*Czpxzpy + dd0*dd0*Czpx2;
        float zn   = fmaxf(sqrtf(Szt2), 1e-8f);
        float izn  = 1.f / zn;
        float mst  = Sst * inv4096;
        float mnam = mst * izn;
        float vnam = (Sst2*inv4096 - mst*mst) * izn * izn;
        float ivn  = rsqrtf(vnam + LN_EPS);
        float k1   = izn * ivn, k0 = -mnam * ivn;
        float srq  = 1.f / fmaxf(sqrtf(a2v.w), 1e-8f);
        float f1 = k1 * ivs, f2 = -f1 * aBar, f3 = k1;
        scal4[r*2 + 0] = make_float4(f1, f2, f3, k0);
        scal4[r*2 + 1] = make_float4(srq, mzv, ivz, 0.f);
    }
    __syncthreads();

    // ================= PASS 2: backward (packed), no syncs =================
    float fsum = 0.f, fsq = 0.f;
    #pragma unroll 1
    for (int r = CHUNK - 1; r >= 0; r--){
        float4 s0 = scal4[r*2 + 0];
        ull f1p = pack2(s0.x, s0.x), f2p = pack2(s0.y, s0.y);
        ull f3p = pack2(s0.z, s0.z), k0p = pack2(s0.w, s0.w);
        const ulonglong2* z2p = (const ulonglong2*)&ztile[r*64 + d0];
        const ulonglong2* q2p = (const ulonglong2*)&qtile[r*64 + d0];
        float vv = vtile[r*64 + p];
        ull nvv2 = pack2(-vv, -vv);
        ull pacc = 0ull;
        #pragma unroll
        for (int j4 = 0; j4 < 4; j4++){
            ulonglong2 zz = z2p[j4];
            ulonglong2 qq = q2p[j4];
            #pragma unroll
            for (int c = 0; c < 2; c++){
                int j = j4*2 + c;
                ull zp = c ? zz.y : zz.x;
                ull qp = c ? qq.y : qq.x;
                ull uu = fmul2(A2[j], wx2[j]);
                ull aa = ffma2(f1p, uu, k0p);
                aa = ffma2(f2p, wx2[j], aa);
                aa = ffma2(f3p, wy2[j], aa);
                ull t = ffma2(aa, wz2[j], ww2[j]);
                pacc = ffma2(qp, t, pacc);
                A2[j] = ffma2(zp, nvv2, A2[j]);    // step back to A_{r-1}
            }
        }
        na_s[r*256 + tid] = hsum2(pacc);
        if (tid < 64){
            float4 s1 = scal4[r*2 + 1];
            float zt = (zc - s1.y)*s1.z*zpxv + zpyv;
            float rr = qtile[r*64 + tid] / fmaxf(zt, 1e-6f);
            fsum += rr; fsq = fmaf(rr, rr, fsq);
            zc -= ztile[r*64 + tid];
        }
    }
    // per-CTA std partials (deterministic, no atomics on values)
    if (w < 2){
        ull s = redsum2(pack2(fsum, fsq));
        if (lane == 0){
            float a, b2; unpack2(s, a, b2);
            db[w*2] = (double)a; db[w*2 + 1] = (double)b2;
        }
    }
    __syncthreads();
    if (tid == 0){
        g_std[pid*2 + 0] = db[0] + db[2];
        g_std[pid*2 + 1] = db[1] + db[3];
        __threadfence();
        unsigned int old = atomicAdd(&g_cnt, 1u);
        sIsLast = ((old % (unsigned)nStd) == (unsigned)(nStd - 1)) ? 1 : 0;
    }
    __syncthreads();

    // ================= EPILOGUE: warp w -> steps w*4 .. w*4+3 ==============
    #pragma unroll
    for (int rr = 0; rr < 4; rr++){
        int r = w*4 + rr;
        float srq = scal4[r*2 + 1].x;
        const float* np = &na_s[r*256];
        float nvA = (np[lane] + np[lane+64] + np[lane+128] + np[lane+192]) * srq;
        float nvB = (np[lane+32] + np[lane+96] + np[lane+160] + np[lane+224]) * srq;
        ull s = redsum2(pack2(nvA + nvB, nvA*nvA + nvB*nvB));
        float s1, s2; unpack2(s, s1, s2);
        float mn = s1 * inv64;
        float iv = rsqrtf(s2*inv64 - mn*mn + LN_EPS);
        float* op = out + xbase + (size_t)r*64;
        op[lane]      = (nvA - mn)*iv*ngA + nbA;
        op[lane + 32] = (nvB - mn)*iv*ngB + nbB;
    }

    // ================= LAST CTA: finalize std in-kernel ====================
    if (sIsLast){
        __threadfence();   // acquire all g_std writes
        double a = 0.0, c = 0.0;
        if (tid < nStd){ a = g_std[tid*2]; c = g_std[tid*2 + 1]; }
        #pragma unroll
        for (int o = 16; o; o >>= 1){
            a += __shfl_xor_sync(0xffffffffu, a, o);
            c += __shfl_xor_sync(0xffffffffu, c, o);
        }
        if (lane == 0){ sred[w*2] = a; sred[w*2 + 1] = c; }
        __syncthreads();
        if (tid == 0){
            double sa = 0.0, sc = 0.0;
            #pragma unroll
            for (int w2 = 0; w2 < 8; w2++){ sa += sred[w2*2]; sc += sred[w2*2 + 1]; }
            int n = nStd * CHUNK * 64;
            double mean = sa / (double)n;
            double var  = (sc - sa*mean) / (double)(n - 1);
            out[outpos] = (float)sqrt(var);
        }
    }
}

// ---------------- launch ----------------
extern "C" void kernel_launch(void* const* d_in, const int* in_sizes, int n_in,
                              void* d_out, int out_size)
{
    const int*   uid   = (const int*)  d_in[0];
    const float* X     = (const float*)d_in[1];
    const float* Pm    = (const float*)d_in[2];
    const float* Sm    = (const float*)d_in[3];
    const float* Wq    = (const float*)d_in[4];
    const float* bq    = (const float*)d_in[5];
    const float* Wk    = (const float*)d_in[6];
    const float* bk    = (const float*)d_in[7];
    const float* Wv    = (const float*)d_in[8];
    const float* bv    = (const float*)d_in[9];
    const float* zg    = (const float*)d_in[10];
    const float* zb    = (const float*)d_in[11];
    const float* sg    = (const float*)d_in[12];
    const float* sb    = (const float*)d_in[13];
    const float* ng    = (const float*)d_in[14];
    const float* nb    = (const float*)d_in[15];
    const float* nag   = (const float*)d_in[16];
    const float* nab   = (const float*)d_in[17];
    const float* pzbuf = (const float*)d_in[18];
    const float* psbuf = (const float*)d_in[19];
    float* out = (float*)d_out;

    int B   = in_sizes[0];
    int L   = in_sizes[1] / (B * 64);
    int NCH = L / CHUNK;
    int LP  = in_sizes[2] / (B * 64);
    int NPH = B * NCH;

    size_t smAll = (size_t)SM_TOTAL * 4;   // ~71 KB dynamic
    cudaFuncSetAttribute(k_all, cudaFuncAttributeMaxDynamicSharedMemorySize, (int)smAll);

    k_all<<<B + NPH, 256, smAll>>>(uid, X, Pm, Sm, Wq, bq, Wk, bk, Wv, bv,
                                   zg, zb, sg, sb, ng, nb, nag, nab,
                                   pzbuf, psbuf, out, NCH, LP, B,
                                   NPH, out_size - 1);
}